// round 1
// baseline (speedup 1.0000x reference)
#include <cuda_runtime.h>
#include <math.h>

#define B_   2
#define S_   2048
#define D_   1024
#define H_   16
#define HD_  64
#define M_   (B_ * S_)      // 4096 rows
#define NQKV (3 * D_)       // 3072

// ---------------- scratch (static device globals; no allocation) ----------
__device__ float g_qkv[(size_t)M_ * NQKV];          // [B*S, 3D]  ~50 MB
__device__ float g_q[(size_t)B_ * H_ * S_ * HD_];   // roped+scaled Q, [B,H,S,hd]
__device__ float g_k[(size_t)B_ * H_ * S_ * HD_];   // roped K,        [B,H,S,hd]
__device__ float g_o[(size_t)M_ * D_];              // attention out,  [B*S, D]

// ---------------------------------------------------------------------------
// SGEMM (NT): C[m,n] = sum_k A[m,k] * W[n,k] (+ bias[n])
// A: [M,K] row-major, W: [N,K] row-major. M,N multiples of 128, K of 16.
// 128x128x16 tile, 256 threads, 8x8 per-thread microtile.
// ---------------------------------------------------------------------------
__global__ void __launch_bounds__(256) sgemm_nt(
    const float* __restrict__ A, const float* __restrict__ W,
    const float* __restrict__ bias, float* __restrict__ C,
    int M, int N, int K)
{
    __shared__ float As[16][132];
    __shared__ float Bs[16][132];
    const int tid = threadIdx.x;
    const int tx  = tid & 15;
    const int ty  = tid >> 4;
    const int m0  = blockIdx.y * 128;
    const int n0  = blockIdx.x * 128;

    const float* Ab = A + (size_t)m0 * K;
    const float* Wb = W + (size_t)n0 * K;

    float acc[8][8];
#pragma unroll
    for (int i = 0; i < 8; ++i)
#pragma unroll
        for (int j = 0; j < 8; ++j) acc[i][j] = 0.f;

    for (int k0 = 0; k0 < K; k0 += 16) {
#pragma unroll
        for (int it = 0; it < 2; ++it) {
            int idx = tid + it * 256;       // 0..511
            int r   = idx >> 2;             // 0..127
            int c   = (idx & 3) << 2;       // 0,4,8,12
            float4 va = *(const float4*)(Ab + (size_t)r * K + k0 + c);
            As[c + 0][r] = va.x; As[c + 1][r] = va.y;
            As[c + 2][r] = va.z; As[c + 3][r] = va.w;
            float4 vb = *(const float4*)(Wb + (size_t)r * K + k0 + c);
            Bs[c + 0][r] = vb.x; Bs[c + 1][r] = vb.y;
            Bs[c + 2][r] = vb.z; Bs[c + 3][r] = vb.w;
        }
        __syncthreads();
#pragma unroll
        for (int k = 0; k < 16; ++k) {
            float a[8], b[8];
            *(float4*)&a[0] = *(const float4*)&As[k][ty * 8];
            *(float4*)&a[4] = *(const float4*)&As[k][ty * 8 + 4];
            *(float4*)&b[0] = *(const float4*)&Bs[k][tx * 8];
            *(float4*)&b[4] = *(const float4*)&Bs[k][tx * 8 + 4];
#pragma unroll
            for (int i = 0; i < 8; ++i)
#pragma unroll
                for (int j = 0; j < 8; ++j)
                    acc[i][j] += a[i] * b[j];
        }
        __syncthreads();
    }

#pragma unroll
    for (int i = 0; i < 8; ++i) {
        int m = m0 + ty * 8 + i;
        float* crow = C + (size_t)m * N + n0 + tx * 8;
#pragma unroll
        for (int j = 0; j < 8; j += 4) {
            float4 v;
            v.x = acc[i][j]; v.y = acc[i][j + 1];
            v.z = acc[i][j + 2]; v.w = acc[i][j + 3];
            if (bias) {
                int n = n0 + tx * 8 + j;
                v.x += bias[n]; v.y += bias[n + 1];
                v.z += bias[n + 2]; v.w += bias[n + 3];
            }
            *(float4*)(crow + j) = v;
        }
    }
}

// ---------------------------------------------------------------------------
// RoPE: read q,k halves of g_qkv, rotate, scatter to [B,H,S,hd] layout.
// Q additionally pre-scaled by 1/sqrt(hd) = 0.125.
// One thread per (b,s,h,j) pair, j in [0,32).
// ---------------------------------------------------------------------------
__global__ void rope_kernel(const float* __restrict__ qkv,
                            float* __restrict__ qo_, float* __restrict__ ko_)
{
    int idx = blockIdx.x * blockDim.x + threadIdx.x;
    if (idx >= B_ * S_ * H_ * 32) return;
    int j = idx & 31;
    int h = (idx >> 5) & (H_ - 1);
    int s = (idx >> 9) & (S_ - 1);
    int b = idx >> 20;

    float t   = (float)(2 * j) * (1.0f / (float)HD_);
    float inv = powf(10000.0f, -t);
    float ang = (float)s * inv;
    float cs  = cosf(ang);
    float sn  = sinf(ang);

    const float* row = qkv + ((size_t)(b * S_ + s)) * NQKV + h * HD_;
    float q1 = row[2 * j],      q2 = row[2 * j + 1];
    float k1 = row[D_ + 2 * j], k2 = row[D_ + 2 * j + 1];

    float* qo = qo_ + (((size_t)(b * H_ + h)) * S_ + s) * HD_;
    float* ko = ko_ + (((size_t)(b * H_ + h)) * S_ + s) * HD_;
    const float qs = 0.125f;  // 1/sqrt(64)
    qo[j]      = (q1 * cs - q2 * sn) * qs;
    qo[32 + j] = (q1 * sn + q2 * cs) * qs;
    ko[j]      = k1 * cs - k2 * sn;
    ko[32 + j] = k1 * sn + k2 * cs;
}

// ---------------------------------------------------------------------------
// Flash attention: one block per (b, h, q-tile of 64). 256 threads.
// Q tile kept transposed in smem; K tile transposed + XOR-swizzled in a
// buffer that is reused for the (transposed, swizzled) P tile. V read
// straight from g_qkv. Online softmax, fp32 throughout.
// smem = 3 * 64*64*4 = 48 KB exactly.
// ---------------------------------------------------------------------------
__global__ void __launch_bounds__(256) attn_kernel(
    const float* __restrict__ q, const float* __restrict__ k,
    const float* __restrict__ qkv, float* __restrict__ o)
{
    __shared__ float Qt[64][64];    // Qt[d][m]
    __shared__ float KPt[64][64];   // Kt[d][n^swz(d)]  /  Pt[n][m^swz(n)]
    __shared__ float Vs[64][64];    // Vs[n][d]

    const int tid = threadIdx.x;
    const int tx  = tid & 15;
    const int ty  = tid >> 4;
    const int q0  = blockIdx.x * 64;
    const int h   = blockIdx.y;
    const int b   = blockIdx.z;
    const size_t bh = ((size_t)b * H_ + h) * S_;

    // load Q tile transposed (once per block; store conflicts amortized)
#pragma unroll
    for (int it = 0; it < 4; ++it) {
        int idx = tid + it * 256;
        int r = idx >> 4;            // 0..63 (query row)
        int c = (idx & 15) << 2;     // 0..60 (d)
        float4 v = *(const float4*)(q + (bh + q0 + r) * HD_ + c);
        Qt[c + 0][r] = v.x; Qt[c + 1][r] = v.y;
        Qt[c + 2][r] = v.z; Qt[c + 3][r] = v.w;
    }

    float oacc[4][4];
    float mi[4], li[4];
#pragma unroll
    for (int i = 0; i < 4; ++i) {
        mi[i] = -1e30f; li[i] = 0.f;
#pragma unroll
        for (int j = 0; j < 4; ++j) oacc[i][j] = 0.f;
    }

    for (int n0 = 0; n0 < S_; n0 += 64) {
        __syncthreads();   // protect KPt/Vs reuse from previous iteration
        // load K tile (transposed + swizzled) and V tile
#pragma unroll
        for (int it = 0; it < 4; ++it) {
            int idx = tid + it * 256;
            int r = idx >> 4;            // key row within tile
            int c = (idx & 15) << 2;     // d
            float4 kv = *(const float4*)(k + (bh + n0 + r) * HD_ + c);
            KPt[c + 0][r ^ ((c + 0) & 60)] = kv.x;
            KPt[c + 1][r ^ ((c + 1) & 60)] = kv.y;
            KPt[c + 2][r ^ ((c + 2) & 60)] = kv.z;
            KPt[c + 3][r ^ ((c + 3) & 60)] = kv.w;
            float4 vv = *(const float4*)(qkv +
                ((size_t)(b * S_ + n0 + r)) * NQKV + 2 * D_ + h * HD_ + c);
            *(float4*)&Vs[r][c] = vv;
        }
        __syncthreads();

        // S = Q K^T  (64x64 tile, 4x4 per thread)
        float s[4][4];
#pragma unroll
        for (int i = 0; i < 4; ++i)
#pragma unroll
            for (int j = 0; j < 4; ++j) s[i][j] = 0.f;

#pragma unroll 8
        for (int d = 0; d < 64; ++d) {
            float4 a4 = *(const float4*)&Qt[d][ty * 4];
            float4 b4 = *(const float4*)&KPt[d][(tx * 4) ^ (d & 60)];
            float a[4] = {a4.x, a4.y, a4.z, a4.w};
            float bb[4] = {b4.x, b4.y, b4.z, b4.w};
#pragma unroll
            for (int i = 0; i < 4; ++i)
#pragma unroll
                for (int j = 0; j < 4; ++j)
                    s[i][j] += a[i] * bb[j];
        }

        // online softmax (row groups = 16 lanes of a half-warp)
#pragma unroll
        for (int i = 0; i < 4; ++i) {
            float rm = fmaxf(fmaxf(s[i][0], s[i][1]), fmaxf(s[i][2], s[i][3]));
            rm = fmaxf(rm, __shfl_xor_sync(0xffffffffu, rm, 1));
            rm = fmaxf(rm, __shfl_xor_sync(0xffffffffu, rm, 2));
            rm = fmaxf(rm, __shfl_xor_sync(0xffffffffu, rm, 4));
            rm = fmaxf(rm, __shfl_xor_sync(0xffffffffu, rm, 8));
            float mn   = fmaxf(mi[i], rm);
            float corr = __expf(mi[i] - mn);
            mi[i] = mn;
            float rs = 0.f;
#pragma unroll
            for (int j = 0; j < 4; ++j) {
                float p = __expf(s[i][j] - mn);
                s[i][j] = p;
                rs += p;
            }
            rs += __shfl_xor_sync(0xffffffffu, rs, 1);
            rs += __shfl_xor_sync(0xffffffffu, rs, 2);
            rs += __shfl_xor_sync(0xffffffffu, rs, 4);
            rs += __shfl_xor_sync(0xffffffffu, rs, 8);
            li[i] = li[i] * corr + rs;
#pragma unroll
            for (int j = 0; j < 4; ++j) oacc[i][j] *= corr;
        }

        __syncthreads();   // done reading K
        // write P transposed + swizzled into the K buffer
#pragma unroll
        for (int j = 0; j < 4; ++j) {
            int n = tx * 4 + j;
            int base = (ty * 4) ^ (n & 60);
            KPt[n][base + 0] = s[0][j];
            KPt[n][base + 1] = s[1][j];
            KPt[n][base + 2] = s[2][j];
            KPt[n][base + 3] = s[3][j];
        }
        __syncthreads();

        // O += P V
#pragma unroll 8
        for (int n = 0; n < 64; ++n) {
            float4 p4 = *(const float4*)&KPt[n][(ty * 4) ^ (n & 60)];
            float4 v4 = *(const float4*)&Vs[n][tx * 4];
            float p[4] = {p4.x, p4.y, p4.z, p4.w};
            float v[4] = {v4.x, v4.y, v4.z, v4.w};
#pragma unroll
            for (int i = 0; i < 4; ++i)
#pragma unroll
                for (int j = 0; j < 4; ++j)
                    oacc[i][j] += p[i] * v[j];
        }
    }

    // epilogue: normalize and scatter to [B*S, D] (head-interleaved) layout
#pragma unroll
    for (int i = 0; i < 4; ++i) {
        float inv = 1.0f / li[i];
        int srow = q0 + ty * 4 + i;
        float4 v;
        v.x = oacc[i][0] * inv; v.y = oacc[i][1] * inv;
        v.z = oacc[i][2] * inv; v.w = oacc[i][3] * inv;
        *(float4*)(o + ((size_t)(b * S_) + srow) * D_ + h * HD_ + tx * 4) = v;
    }
}

// ---------------------------------------------------------------------------
extern "C" void kernel_launch(void* const* d_in, const int* in_sizes, int n_in,
                              void* d_out, int out_size)
{
    (void)in_sizes; (void)n_in; (void)out_size;
    const float* x     = (const float*)d_in[0];
    const float* w_qkv = (const float*)d_in[1];
    const float* w_out = (const float*)d_in[2];
    const float* b_out = (const float*)d_in[3];
    float* out = (float*)d_out;

    float *p_qkv, *p_q, *p_k, *p_o;
    cudaGetSymbolAddress((void**)&p_qkv, g_qkv);
    cudaGetSymbolAddress((void**)&p_q,   g_q);
    cudaGetSymbolAddress((void**)&p_k,   g_k);
    cudaGetSymbolAddress((void**)&p_o,   g_o);

    // 1) QKV projection: [4096,1024] x [3072,1024]^T -> [4096,3072]
    {
        dim3 grid(NQKV / 128, M_ / 128);
        sgemm_nt<<<grid, 256>>>(x, w_qkv, nullptr, p_qkv, M_, NQKV, D_);
    }
    // 2) RoPE + head transpose (+ q scaling)
    {
        int total = B_ * S_ * H_ * 32;
        rope_kernel<<<(total + 255) / 256, 256>>>(p_qkv, p_q, p_k);
    }
    // 3) flash attention
    {
        dim3 grid(S_ / 64, H_, B_);
        attn_kernel<<<grid, 256>>>(p_q, p_k, p_qkv, p_o);
    }
    // 4) output projection + bias: [4096,1024] x [1024,1024]^T -> out
    {
        dim3 grid(D_ / 128, M_ / 128);
        sgemm_nt<<<grid, 256>>>(p_o, w_out, b_out, out, M_, D_, D_);
    }
}

// round 3
// speedup vs baseline: 2.7338x; 2.7338x over previous
#include <cuda_runtime.h>
#include <cuda_bf16.h>
#include <math.h>
#include <cstdint>

#define B_   2
#define S_   2048
#define D_   1024
#define H_   16
#define HD_  64
#define M_   (B_ * S_)      // 4096
#define NQKV (3 * D_)       // 3072

// ---------------- scratch (static device globals; no allocation) ----------
__device__ float g_qkv[(size_t)M_ * NQKV];                      // fp32 [B*S, 3D]
__device__ __nv_bfloat16 g_xh[(size_t)M_ * D_],    g_xl[(size_t)M_ * D_];
__device__ __nv_bfloat16 g_wqh[(size_t)NQKV * D_], g_wql[(size_t)NQKV * D_];
__device__ __nv_bfloat16 g_woh[(size_t)D_ * D_],   g_wol[(size_t)D_ * D_];
// roped q/k and v in [B,H,S,64] layout, hi/lo bf16 (each 4M elements)
__device__ __nv_bfloat16 g_qhb[(size_t)M_ * D_], g_qlb[(size_t)M_ * D_];
__device__ __nv_bfloat16 g_khb[(size_t)M_ * D_], g_klb[(size_t)M_ * D_];
__device__ __nv_bfloat16 g_vhb[(size_t)M_ * D_], g_vlb[(size_t)M_ * D_];
// attention output hi/lo bf16 in [B*S, D] layout
__device__ __nv_bfloat16 g_ohb[(size_t)M_ * D_], g_olb[(size_t)M_ * D_];

// =====================  helpers  ===========================================
__device__ __forceinline__ uint32_t smem_u32(const void* p) {
    uint32_t a;
    asm("{ .reg .u64 t; cvta.to.shared.u64 t, %1; cvt.u32.u64 %0, t; }"
        : "=r"(a) : "l"(p));
    return a;
}
__device__ __forceinline__ void ldm_x4(uint32_t (&r)[4], uint32_t addr) {
    asm volatile("ldmatrix.sync.aligned.m8n8.x4.shared.b16 {%0,%1,%2,%3}, [%4];"
        : "=r"(r[0]), "=r"(r[1]), "=r"(r[2]), "=r"(r[3]) : "r"(addr));
}
__device__ __forceinline__ void ldm_x4_t(uint32_t (&r)[4], uint32_t addr) {
    asm volatile("ldmatrix.sync.aligned.m8n8.x4.trans.shared.b16 {%0,%1,%2,%3}, [%4];"
        : "=r"(r[0]), "=r"(r[1]), "=r"(r[2]), "=r"(r[3]) : "r"(addr));
}
__device__ __forceinline__ void mma_bf16(float (&d)[4], const uint32_t (&a)[4],
                                         const uint32_t b0, const uint32_t b1) {
    asm volatile(
        "mma.sync.aligned.m16n8k16.row.col.f32.bf16.bf16.f32 "
        "{%0,%1,%2,%3}, {%4,%5,%6,%7}, {%8,%9}, {%0,%1,%2,%3};"
        : "+f"(d[0]), "+f"(d[1]), "+f"(d[2]), "+f"(d[3])
        : "r"(a[0]), "r"(a[1]), "r"(a[2]), "r"(a[3]), "r"(b0), "r"(b1));
}
__device__ __forceinline__ void split1(float x, __nv_bfloat16& h, __nv_bfloat16& l) {
    h = __float2bfloat16_rn(x);
    l = __float2bfloat16_rn(x - __bfloat162float(h));
}
__device__ __forceinline__ void split_pack(float x0, float x1,
                                           uint32_t& hi, uint32_t& lo) {
    __nv_bfloat16 h0, l0, h1, l1;
    split1(x0, h0, l0);
    split1(x1, h1, l1);
    __nv_bfloat162 hp(h0, h1), lp(l0, l1);
    hi = *(uint32_t*)&hp;
    lo = *(uint32_t*)&lp;
}

// ---------------------------------------------------------------------------
// split fp32 -> (hi, lo) bf16, vectorized
// ---------------------------------------------------------------------------
__global__ void split_bf16(const float* __restrict__ src,
                           __nv_bfloat16* __restrict__ hi,
                           __nv_bfloat16* __restrict__ lo, int n4)
{
    int i = blockIdx.x * blockDim.x + threadIdx.x;
    if (i >= n4) return;
    float4 v = ((const float4*)src)[i];
    uint32_t h0, l0, h1, l1;
    split_pack(v.x, v.y, h0, l0);
    split_pack(v.z, v.w, h1, l1);
    ((uint32_t*)hi)[i * 2 + 0] = h0;
    ((uint32_t*)hi)[i * 2 + 1] = h1;
    ((uint32_t*)lo)[i * 2 + 0] = l0;
    ((uint32_t*)lo)[i * 2 + 1] = l1;
}

// ---------------------------------------------------------------------------
// GEMM (NT) via mma.sync bf16x3: C[m,n] = sum_k A[m,k]*B[n,k] (+bias)
// CTA 128x128, kchunk 64, 8 warps each 64x32. smem 64KB dynamic.
// ---------------------------------------------------------------------------
#define SA_H 0
#define SA_L 16384
#define SB_H 32768
#define SB_L 49152
#define GEMM_SMEM 65536

__global__ void __launch_bounds__(256) gemm_mma(
    const __nv_bfloat16* __restrict__ Ah, const __nv_bfloat16* __restrict__ Al,
    const __nv_bfloat16* __restrict__ Bh, const __nv_bfloat16* __restrict__ Bl,
    const float* __restrict__ bias, float* __restrict__ C,
    int M, int N, int K)
{
    extern __shared__ char sm[];
    const uint32_t sb = smem_u32(sm);
    const int tid  = threadIdx.x;
    const int lane = tid & 31;
    const int w    = tid >> 5;
    const int m0 = blockIdx.y * 128;
    const int n0 = blockIdx.x * 128;
    const int wm = (w & 1) * 64;
    const int wn = (w >> 1) * 32;

    float acc[4][4][4];
#pragma unroll
    for (int mi = 0; mi < 4; ++mi)
#pragma unroll
        for (int ni = 0; ni < 4; ++ni)
#pragma unroll
            for (int t = 0; t < 4; ++t) acc[mi][ni][t] = 0.f;

    for (int kc = 0; kc < K; kc += 64) {
#pragma unroll
        for (int it = 0; it < 4; ++it) {
            int idx = tid + it * 256;          // 0..1023: 128 rows x 8 chunks
            int r = idx >> 3, g = idx & 7;
            uint32_t so = r * 128 + (((uint32_t)(g ^ (r & 7))) << 4);
            size_t ga = (size_t)(m0 + r) * K + kc + g * 8;
            size_t gb = (size_t)(n0 + r) * K + kc + g * 8;
            *(uint4*)(sm + SA_H + so) = *(const uint4*)(Ah + ga);
            *(uint4*)(sm + SA_L + so) = *(const uint4*)(Al + ga);
            *(uint4*)(sm + SB_H + so) = *(const uint4*)(Bh + gb);
            *(uint4*)(sm + SB_L + so) = *(const uint4*)(Bl + gb);
        }
        __syncthreads();

#pragma unroll
        for (int ks = 0; ks < 4; ++ks) {
            // A fragments (hi & lo)
            uint32_t ah[4][4], al[4][4];
            const int ar = wm + (lane & 7) + ((lane >> 3) & 1) * 8;
            const int ag = ks * 2 + (lane >> 4);
#pragma unroll
            for (int mi = 0; mi < 4; ++mi) {
                int r = ar + mi * 16;
                uint32_t ad = sb + SA_H + r * 128 + (((uint32_t)(ag ^ (r & 7))) << 4);
                ldm_x4(ah[mi], ad);
                ldm_x4(al[mi], ad + 16384);
            }
            // B fragments (hi & lo), pairs of n8
            uint32_t bh[4][2], bl[4][2];
            const int br = wn + ((lane >> 4) & 1) * 8 + (lane & 7);
            const int bg = ks * 2 + ((lane >> 3) & 1);
#pragma unroll
            for (int pi = 0; pi < 2; ++pi) {
                int r = br + pi * 16;
                uint32_t ad = sb + SB_H + r * 128 + (((uint32_t)(bg ^ (r & 7))) << 4);
                uint32_t t[4];
                ldm_x4(t, ad);
                bh[pi*2][0]=t[0]; bh[pi*2][1]=t[1]; bh[pi*2+1][0]=t[2]; bh[pi*2+1][1]=t[3];
                ldm_x4(t, ad + 16384);
                bl[pi*2][0]=t[0]; bl[pi*2][1]=t[1]; bl[pi*2+1][0]=t[2]; bl[pi*2+1][1]=t[3];
            }
#pragma unroll
            for (int mi = 0; mi < 4; ++mi)
#pragma unroll
                for (int ni = 0; ni < 4; ++ni) {
                    mma_bf16(acc[mi][ni], ah[mi], bh[ni][0], bh[ni][1]);
                    mma_bf16(acc[mi][ni], ah[mi], bl[ni][0], bl[ni][1]);
                    mma_bf16(acc[mi][ni], al[mi], bh[ni][0], bh[ni][1]);
                }
        }
        __syncthreads();
    }

    // epilogue
    const int r0 = lane >> 2;
    const int c0 = (lane & 3) * 2;
#pragma unroll
    for (int mi = 0; mi < 4; ++mi) {
#pragma unroll
        for (int ni = 0; ni < 4; ++ni) {
            int m = m0 + wm + mi * 16 + r0;
            int n = n0 + wn + ni * 8 + c0;
            float b0 = bias ? bias[n] : 0.f;
            float b1 = bias ? bias[n + 1] : 0.f;
            float2 v0 = {acc[mi][ni][0] + b0, acc[mi][ni][1] + b1};
            float2 v1 = {acc[mi][ni][2] + b0, acc[mi][ni][3] + b1};
            *(float2*)(C + (size_t)m * N + n)       = v0;
            *(float2*)(C + (size_t)(m + 8) * N + n) = v1;
        }
    }
}

// ---------------------------------------------------------------------------
// RoPE + split: reads fp32 qkv, writes roped q/k and v as hi/lo bf16 in
// [B,H,S,64]. Q pre-scaled by 1/sqrt(64).
// ---------------------------------------------------------------------------
__global__ void rope_split(const float* __restrict__ qkv,
                           __nv_bfloat16* __restrict__ qh, __nv_bfloat16* __restrict__ ql,
                           __nv_bfloat16* __restrict__ kh, __nv_bfloat16* __restrict__ kl,
                           __nv_bfloat16* __restrict__ vh, __nv_bfloat16* __restrict__ vl)
{
    int idx = blockIdx.x * blockDim.x + threadIdx.x;
    if (idx >= B_ * S_ * H_ * 32) return;
    int j = idx & 31;
    int h = (idx >> 5) & (H_ - 1);
    int s = (idx >> 9) & (S_ - 1);
    int b = idx >> 20;

    float t   = (float)(2 * j) * (1.0f / (float)HD_);
    float inv = powf(10000.0f, -t);
    float ang = (float)s * inv;
    float cs  = cosf(ang);
    float sn  = sinf(ang);

    const float* row = qkv + ((size_t)(b * S_ + s)) * NQKV + h * HD_;
    float q1 = row[2 * j],          q2 = row[2 * j + 1];
    float k1 = row[D_ + 2 * j],     k2 = row[D_ + 2 * j + 1];
    float v1 = row[2 * D_ + 2 * j], v2 = row[2 * D_ + 2 * j + 1];

    size_t o = (((size_t)(b * H_ + h)) * S_ + s) * HD_;
    const float qs = 0.125f;
    float qa = (q1 * cs - q2 * sn) * qs;
    float qb = (q1 * sn + q2 * cs) * qs;
    float ka = k1 * cs - k2 * sn;
    float kb = k1 * sn + k2 * cs;

    __nv_bfloat16 hh, ll;
    split1(qa, hh, ll); qh[o + j] = hh;      ql[o + j] = ll;
    split1(qb, hh, ll); qh[o + 32 + j] = hh; ql[o + 32 + j] = ll;
    split1(ka, hh, ll); kh[o + j] = hh;      kl[o + j] = ll;
    split1(kb, hh, ll); kh[o + 32 + j] = hh; kl[o + 32 + j] = ll;
    uint32_t vhp, vlp;
    split_pack(v1, v2, vhp, vlp);
    *(uint32_t*)(vh + o + 2 * j) = vhp;
    *(uint32_t*)(vl + o + 2 * j) = vlp;
}

// ---------------------------------------------------------------------------
// Flash attention via mma.sync bf16x3.
// CTA: 256 thr (8 warps), q-tile 128 (16 rows/warp), kv-tile 64.
// smem: K hi/lo + V hi/lo (4 x 8KB) at 0..32KB, Q staging hi/lo at 32..64KB.
// ---------------------------------------------------------------------------
#define AT_KH 0
#define AT_KL 8192
#define AT_VH 16384
#define AT_VL 24576
#define AT_QH 32768
#define AT_QL 49152
#define ATT_SMEM 65536

__global__ void __launch_bounds__(256) attn_mma(
    const __nv_bfloat16* __restrict__ qh_, const __nv_bfloat16* __restrict__ ql_,
    const __nv_bfloat16* __restrict__ kh_, const __nv_bfloat16* __restrict__ kl_,
    const __nv_bfloat16* __restrict__ vh_, const __nv_bfloat16* __restrict__ vl_,
    __nv_bfloat16* __restrict__ oh_, __nv_bfloat16* __restrict__ ol_)
{
    extern __shared__ char sm[];
    const uint32_t sb = smem_u32(sm);
    const int tid  = threadIdx.x;
    const int lane = tid & 31;
    const int w    = tid >> 5;
    const int q0 = blockIdx.x * 128;
    const int h  = blockIdx.y;
    const int b  = blockIdx.z;
    const size_t bh = ((size_t)(b * H_ + h)) * S_;

    // stage Q tile (hi/lo) into smem, swizzled
#pragma unroll
    for (int it = 0; it < 4; ++it) {
        int idx = tid + it * 256;      // 128 rows x 8 chunks
        int r = idx >> 3, g = idx & 7;
        uint32_t so = AT_QH + r * 128 + (((uint32_t)(g ^ (r & 7))) << 4);
        size_t ga = (bh + q0 + r) * HD_ + g * 8;
        *(uint4*)(sm + so)         = *(const uint4*)(qh_ + ga);
        *(uint4*)(sm + so + 16384) = *(const uint4*)(ql_ + ga);
    }
    __syncthreads();

    // persistent Q fragments: 4 k16-frags x (hi, lo)
    uint32_t qh[4][4], ql[4][4];
    {
        const int ar = w * 16 + (lane & 7) + ((lane >> 3) & 1) * 8;
#pragma unroll
        for (int kf = 0; kf < 4; ++kf) {
            int g = kf * 2 + (lane >> 4);
            uint32_t ad = sb + AT_QH + ar * 128 + (((uint32_t)(g ^ (ar & 7))) << 4);
            ldm_x4(qh[kf], ad);
            ldm_x4(ql[kf], ad + 16384);
        }
    }

    float oacc[8][4];
    float mx[2] = {-1e30f, -1e30f};
    float li[2] = {0.f, 0.f};
#pragma unroll
    for (int dj = 0; dj < 8; ++dj)
#pragma unroll
        for (int t = 0; t < 4; ++t) oacc[dj][t] = 0.f;

    for (int n0k = 0; n0k < S_; n0k += 64) {
        __syncthreads();
#pragma unroll
        for (int it = 0; it < 2; ++it) {
            int idx = tid + it * 256;  // 64 rows x 8 chunks
            int r = idx >> 3, g = idx & 7;
            uint32_t so = r * 128 + (((uint32_t)(g ^ (r & 7))) << 4);
            size_t ga = (bh + n0k + r) * HD_ + g * 8;
            *(uint4*)(sm + AT_KH + so) = *(const uint4*)(kh_ + ga);
            *(uint4*)(sm + AT_KL + so) = *(const uint4*)(kl_ + ga);
            *(uint4*)(sm + AT_VH + so) = *(const uint4*)(vh_ + ga);
            *(uint4*)(sm + AT_VL + so) = *(const uint4*)(vl_ + ga);
        }
        __syncthreads();

        // S = Q K^T  (16 x 64 per warp)
        float s[8][4];
#pragma unroll
        for (int nj = 0; nj < 8; ++nj)
#pragma unroll
            for (int t = 0; t < 4; ++t) s[nj][t] = 0.f;

#pragma unroll
        for (int ks = 0; ks < 4; ++ks) {
            const int br = ((lane >> 4) & 1) * 8 + (lane & 7);
            const int bg = ks * 2 + ((lane >> 3) & 1);
#pragma unroll
            for (int pi = 0; pi < 4; ++pi) {
                int r = br + pi * 16;
                uint32_t ad = sb + AT_KH + r * 128 + (((uint32_t)(bg ^ (r & 7))) << 4);
                uint32_t th[4], tl[4];
                ldm_x4(th, ad);
                ldm_x4(tl, ad + 8192);
                mma_bf16(s[pi*2],   qh[ks], th[0], th[1]);
                mma_bf16(s[pi*2],   qh[ks], tl[0], tl[1]);
                mma_bf16(s[pi*2],   ql[ks], th[0], th[1]);
                mma_bf16(s[pi*2+1], qh[ks], th[2], th[3]);
                mma_bf16(s[pi*2+1], qh[ks], tl[2], tl[3]);
                mma_bf16(s[pi*2+1], ql[ks], th[2], th[3]);
            }
        }

        // online softmax (2 thread-rows)
#pragma unroll
        for (int ri = 0; ri < 2; ++ri) {
            float rm = -1e30f;
#pragma unroll
            for (int nj = 0; nj < 8; ++nj)
                rm = fmaxf(rm, fmaxf(s[nj][ri*2], s[nj][ri*2+1]));
            rm = fmaxf(rm, __shfl_xor_sync(0xffffffffu, rm, 1));
            rm = fmaxf(rm, __shfl_xor_sync(0xffffffffu, rm, 2));
            float mn   = fmaxf(mx[ri], rm);
            float corr = __expf(mx[ri] - mn);
            mx[ri] = mn;
            float rs = 0.f;
#pragma unroll
            for (int nj = 0; nj < 8; ++nj) {
                float p0 = __expf(s[nj][ri*2]   - mn);
                float p1 = __expf(s[nj][ri*2+1] - mn);
                s[nj][ri*2] = p0; s[nj][ri*2+1] = p1;
                rs += p0 + p1;
            }
            rs += __shfl_xor_sync(0xffffffffu, rs, 1);
            rs += __shfl_xor_sync(0xffffffffu, rs, 2);
            li[ri] = li[ri] * corr + rs;
#pragma unroll
            for (int dj = 0; dj < 8; ++dj) {
                oacc[dj][ri*2]   *= corr;
                oacc[dj][ri*2+1] *= corr;
            }
        }

        // O += P V
#pragma unroll
        for (int ks = 0; ks < 4; ++ks) {
            // pack P k16-frag (hi/lo) from S registers (C-layout == A-layout)
            uint32_t ph[4], pl[4];
            split_pack(s[ks*2][0],   s[ks*2][1],   ph[0], pl[0]);
            split_pack(s[ks*2][2],   s[ks*2][3],   ph[1], pl[1]);
            split_pack(s[ks*2+1][0], s[ks*2+1][1], ph[2], pl[2]);
            split_pack(s[ks*2+1][2], s[ks*2+1][3], ph[3], pl[3]);

            const int vr = ks * 16 + ((lane >> 3) & 1) * 8 + (lane & 7);
#pragma unroll
            for (int pj = 0; pj < 4; ++pj) {
                int gc = pj * 2 + (lane >> 4);
                uint32_t ad = sb + AT_VH + vr * 128 + (((uint32_t)(gc ^ (vr & 7))) << 4);
                uint32_t th[4], tl[4];
                ldm_x4_t(th, ad);
                ldm_x4_t(tl, ad + 8192);
                mma_bf16(oacc[pj*2],   ph, th[0], th[1]);
                mma_bf16(oacc[pj*2],   ph, tl[0], tl[1]);
                mma_bf16(oacc[pj*2],   pl, th[0], th[1]);
                mma_bf16(oacc[pj*2+1], ph, th[2], th[3]);
                mma_bf16(oacc[pj*2+1], ph, tl[2], tl[3]);
                mma_bf16(oacc[pj*2+1], pl, th[2], th[3]);
            }
        }
    }

    // epilogue: normalize, split to bf16 hi/lo, write [B*S, D]
#pragma unroll
    for (int ri = 0; ri < 2; ++ri) {
        float inv = 1.0f / li[ri];
        int srow = q0 + w * 16 + (lane >> 2) + ri * 8;
        size_t rowo = ((size_t)(b * S_) + srow) * D_ + h * HD_;
#pragma unroll
        for (int dj = 0; dj < 8; ++dj) {
            int c = dj * 8 + (lane & 3) * 2;
            uint32_t hp, lp;
            split_pack(oacc[dj][ri*2] * inv, oacc[dj][ri*2+1] * inv, hp, lp);
            *(uint32_t*)(oh_ + rowo + c) = hp;
            *(uint32_t*)(ol_ + rowo + c) = lp;
        }
    }
}

// ---------------------------------------------------------------------------
extern "C" void kernel_launch(void* const* d_in, const int* in_sizes, int n_in,
                              void* d_out, int out_size)
{
    (void)in_sizes; (void)n_in; (void)out_size;
    const float* x     = (const float*)d_in[0];
    const float* w_qkv = (const float*)d_in[1];
    const float* w_out = (const float*)d_in[2];
    const float* b_out = (const float*)d_in[3];
    float* out = (float*)d_out;

    float* p_qkv;
    cudaGetSymbolAddress((void**)&p_qkv, g_qkv);
    __nv_bfloat16 *xh, *xl, *wqh, *wql, *woh, *wol;
    __nv_bfloat16 *qh, *ql, *kh, *kl, *vh, *vl, *oh, *ol;
    cudaGetSymbolAddress((void**)&xh,  g_xh);
    cudaGetSymbolAddress((void**)&xl,  g_xl);
    cudaGetSymbolAddress((void**)&wqh, g_wqh);
    cudaGetSymbolAddress((void**)&wql, g_wql);
    cudaGetSymbolAddress((void**)&woh, g_woh);
    cudaGetSymbolAddress((void**)&wol, g_wol);
    cudaGetSymbolAddress((void**)&qh,  g_qhb);
    cudaGetSymbolAddress((void**)&ql,  g_qlb);
    cudaGetSymbolAddress((void**)&kh,  g_khb);
    cudaGetSymbolAddress((void**)&kl,  g_klb);
    cudaGetSymbolAddress((void**)&vh,  g_vhb);
    cudaGetSymbolAddress((void**)&vl,  g_vlb);
    cudaGetSymbolAddress((void**)&oh,  g_ohb);
    cudaGetSymbolAddress((void**)&ol,  g_olb);

    cudaFuncSetAttribute(gemm_mma,
        cudaFuncAttributeMaxDynamicSharedMemorySize, GEMM_SMEM);
    cudaFuncSetAttribute(attn_mma,
        cudaFuncAttributeMaxDynamicSharedMemorySize, ATT_SMEM);

    // 0) split x and weights into bf16 hi+lo
    {
        int n4;
        n4 = (M_ * D_) / 4;
        split_bf16<<<(n4 + 255) / 256, 256>>>(x, xh, xl, n4);
        n4 = (NQKV * D_) / 4;
        split_bf16<<<(n4 + 255) / 256, 256>>>(w_qkv, wqh, wql, n4);
        n4 = (D_ * D_) / 4;
        split_bf16<<<(n4 + 255) / 256, 256>>>(w_out, woh, wol, n4);
    }
    // 1) QKV projection
    {
        dim3 grid(NQKV / 128, M_ / 128);
        gemm_mma<<<grid, 256, GEMM_SMEM>>>(xh, xl, wqh, wql, nullptr, p_qkv,
                                           M_, NQKV, D_);
    }
    // 2) RoPE + split to bf16 hi/lo [B,H,S,64]
    {
        int total = B_ * S_ * H_ * 32;
        rope_split<<<(total + 255) / 256, 256>>>(p_qkv, qh, ql, kh, kl, vh, vl);
    }
    // 3) flash attention (tensor cores), writes o hi/lo bf16
    {
        dim3 grid(S_ / 128, H_, B_);
        attn_mma<<<grid, 256, ATT_SMEM>>>(qh, ql, kh, kl, vh, vl, oh, ol);
    }
    // 4) output projection + bias
    {
        dim3 grid(D_ / 128, M_ / 128);
        gemm_mma<<<grid, 256, GEMM_SMEM>>>(oh, ol, woh, wol, b_out, out,
                                           M_, D_, D_);
    }
}

// round 4
// speedup vs baseline: 3.0712x; 1.1234x over previous
#include <cuda_runtime.h>
#include <cuda_bf16.h>
#include <math.h>
#include <cstdint>

#define B_   2
#define S_   2048
#define D_   1024
#define H_   16
#define HD_  64
#define M_   (B_ * S_)      // 4096
#define NQKV (3 * D_)       // 3072

// ---------------- scratch (static device globals; no allocation) ----------
__device__ float g_qkv[(size_t)M_ * NQKV];                      // fp32 [B*S, 3D]
__device__ __nv_bfloat16 g_xh[(size_t)M_ * D_],    g_xl[(size_t)M_ * D_];
__device__ __nv_bfloat16 g_wqh[(size_t)NQKV * D_], g_wql[(size_t)NQKV * D_];
__device__ __nv_bfloat16 g_woh[(size_t)D_ * D_],   g_wol[(size_t)D_ * D_];
__device__ __nv_bfloat16 g_qhb[(size_t)M_ * D_], g_qlb[(size_t)M_ * D_];
__device__ __nv_bfloat16 g_khb[(size_t)M_ * D_], g_klb[(size_t)M_ * D_];
__device__ __nv_bfloat16 g_vhb[(size_t)M_ * D_], g_vlb[(size_t)M_ * D_];
__device__ __nv_bfloat16 g_ohb[(size_t)M_ * D_], g_olb[(size_t)M_ * D_];

// =====================  helpers  ===========================================
__device__ __forceinline__ uint32_t smem_u32(const void* p) {
    uint32_t a;
    asm("{ .reg .u64 t; cvta.to.shared.u64 t, %1; cvt.u32.u64 %0, t; }"
        : "=r"(a) : "l"(p));
    return a;
}
__device__ __forceinline__ void ldm_x4(uint32_t (&r)[4], uint32_t addr) {
    asm volatile("ldmatrix.sync.aligned.m8n8.x4.shared.b16 {%0,%1,%2,%3}, [%4];"
        : "=r"(r[0]), "=r"(r[1]), "=r"(r[2]), "=r"(r[3]) : "r"(addr));
}
__device__ __forceinline__ void ldm_x4_t(uint32_t (&r)[4], uint32_t addr) {
    asm volatile("ldmatrix.sync.aligned.m8n8.x4.trans.shared.b16 {%0,%1,%2,%3}, [%4];"
        : "=r"(r[0]), "=r"(r[1]), "=r"(r[2]), "=r"(r[3]) : "r"(addr));
}
__device__ __forceinline__ void mma_bf16(float (&d)[4], const uint32_t (&a)[4],
                                         const uint32_t b0, const uint32_t b1) {
    asm volatile(
        "mma.sync.aligned.m16n8k16.row.col.f32.bf16.bf16.f32 "
        "{%0,%1,%2,%3}, {%4,%5,%6,%7}, {%8,%9}, {%0,%1,%2,%3};"
        : "+f"(d[0]), "+f"(d[1]), "+f"(d[2]), "+f"(d[3])
        : "r"(a[0]), "r"(a[1]), "r"(a[2]), "r"(a[3]), "r"(b0), "r"(b1));
}
__device__ __forceinline__ void cp16(uint32_t saddr, const void* gaddr) {
    asm volatile("cp.async.cg.shared.global [%0], [%1], 16;"
        :: "r"(saddr), "l"(gaddr));
}
#define CP_COMMIT() asm volatile("cp.async.commit_group;" ::: "memory")
#define CP_WAIT(n)  asm volatile("cp.async.wait_group %0;" :: "n"(n) : "memory")

__device__ __forceinline__ void split1(float x, __nv_bfloat16& h, __nv_bfloat16& l) {
    h = __float2bfloat16_rn(x);
    l = __float2bfloat16_rn(x - __bfloat162float(h));
}
__device__ __forceinline__ void split_pack(float x0, float x1,
                                           uint32_t& hi, uint32_t& lo) {
    __nv_bfloat16 h0, l0, h1, l1;
    split1(x0, h0, l0);
    split1(x1, h1, l1);
    __nv_bfloat162 hp(h0, h1), lp(l0, l1);
    hi = *(uint32_t*)&hp;
    lo = *(uint32_t*)&lp;
}

// ---------------------------------------------------------------------------
__global__ void split_bf16(const float* __restrict__ src,
                           __nv_bfloat16* __restrict__ hi,
                           __nv_bfloat16* __restrict__ lo, int n4)
{
    int i = blockIdx.x * blockDim.x + threadIdx.x;
    if (i >= n4) return;
    float4 v = ((const float4*)src)[i];
    uint32_t h0, l0, h1, l1;
    split_pack(v.x, v.y, h0, l0);
    split_pack(v.z, v.w, h1, l1);
    ((uint32_t*)hi)[i * 2 + 0] = h0;
    ((uint32_t*)hi)[i * 2 + 1] = h1;
    ((uint32_t*)lo)[i * 2 + 0] = l0;
    ((uint32_t*)lo)[i * 2 + 1] = l1;
}

// ---------------------------------------------------------------------------
// GEMM (NT) via mma.sync bf16x3, 2-stage cp.async pipeline.
// CTA 128x128, kchunk 64, 8 warps each 64x32. smem 2 x 64KB.
// ---------------------------------------------------------------------------
#define SA_H 0
#define SA_L 16384
#define SB_H 32768
#define SB_L 49152
#define GSTG 65536
#define GEMM_SMEM (2 * GSTG)

__global__ void __launch_bounds__(256) gemm_mma(
    const __nv_bfloat16* __restrict__ Ah, const __nv_bfloat16* __restrict__ Al,
    const __nv_bfloat16* __restrict__ Bh, const __nv_bfloat16* __restrict__ Bl,
    const float* __restrict__ bias, float* __restrict__ C,
    int M, int N, int K)
{
    extern __shared__ char sm[];
    const uint32_t sb = smem_u32(sm);
    const int tid  = threadIdx.x;
    const int lane = tid & 31;
    const int w    = tid >> 5;
    const int m0 = blockIdx.y * 128;
    const int n0 = blockIdx.x * 128;
    const int wm = (w & 1) * 64;
    const int wn = (w >> 1) * 32;

    // per-thread load geometry (16 cp.asyncs per stage per thread)
    const int lr = tid >> 1;                 // 0..127 (row pair base)
    // actually use the same mapping as before: idx = tid + it*256
    float acc[4][4][4];
#pragma unroll
    for (int mi = 0; mi < 4; ++mi)
#pragma unroll
        for (int ni = 0; ni < 4; ++ni)
#pragma unroll
            for (int t = 0; t < 4; ++t) acc[mi][ni][t] = 0.f;
    (void)lr;

    const int nch = K >> 6;

    auto issue_stage = [&](int kc, int stg) {
        uint32_t st = sb + stg * GSTG;
#pragma unroll
        for (int it = 0; it < 4; ++it) {
            int idx = tid + it * 256;
            int r = idx >> 3, g = idx & 7;
            uint32_t so = r * 128 + (((uint32_t)(g ^ (r & 7))) << 4);
            size_t ga = (size_t)(m0 + r) * K + kc * 64 + g * 8;
            size_t gb = (size_t)(n0 + r) * K + kc * 64 + g * 8;
            cp16(st + SA_H + so, Ah + ga);
            cp16(st + SA_L + so, Al + ga);
            cp16(st + SB_H + so, Bh + gb);
            cp16(st + SB_L + so, Bl + gb);
        }
        CP_COMMIT();
    };

    issue_stage(0, 0);

    for (int kc = 0; kc < nch; ++kc) {
        if (kc + 1 < nch) {
            issue_stage(kc + 1, (kc + 1) & 1);
            CP_WAIT(1);
        } else {
            CP_WAIT(0);
        }
        __syncthreads();
        const uint32_t st = sb + (kc & 1) * GSTG;

#pragma unroll
        for (int ks = 0; ks < 4; ++ks) {
            uint32_t ah[4][4], al[4][4];
            const int ar = wm + (lane & 7) + ((lane >> 3) & 1) * 8;
            const int ag = ks * 2 + (lane >> 4);
#pragma unroll
            for (int mi = 0; mi < 4; ++mi) {
                int r = ar + mi * 16;
                uint32_t ad = st + SA_H + r * 128 + (((uint32_t)(ag ^ (r & 7))) << 4);
                ldm_x4(ah[mi], ad);
                ldm_x4(al[mi], ad + 16384);
            }
            uint32_t bh[4][2], bl[4][2];
            const int br = wn + ((lane >> 4) & 1) * 8 + (lane & 7);
            const int bg = ks * 2 + ((lane >> 3) & 1);
#pragma unroll
            for (int pi = 0; pi < 2; ++pi) {
                int r = br + pi * 16;
                uint32_t ad = st + SB_H + r * 128 + (((uint32_t)(bg ^ (r & 7))) << 4);
                uint32_t t[4];
                ldm_x4(t, ad);
                bh[pi*2][0]=t[0]; bh[pi*2][1]=t[1]; bh[pi*2+1][0]=t[2]; bh[pi*2+1][1]=t[3];
                ldm_x4(t, ad + 16384);
                bl[pi*2][0]=t[0]; bl[pi*2][1]=t[1]; bl[pi*2+1][0]=t[2]; bl[pi*2+1][1]=t[3];
            }
#pragma unroll
            for (int mi = 0; mi < 4; ++mi)
#pragma unroll
                for (int ni = 0; ni < 4; ++ni) {
                    mma_bf16(acc[mi][ni], ah[mi], bh[ni][0], bh[ni][1]);
                    mma_bf16(acc[mi][ni], ah[mi], bl[ni][0], bl[ni][1]);
                    mma_bf16(acc[mi][ni], al[mi], bh[ni][0], bh[ni][1]);
                }
        }
        __syncthreads();
    }

    const int r0 = lane >> 2;
    const int c0 = (lane & 3) * 2;
#pragma unroll
    for (int mi = 0; mi < 4; ++mi) {
#pragma unroll
        for (int ni = 0; ni < 4; ++ni) {
            int m = m0 + wm + mi * 16 + r0;
            int n = n0 + wn + ni * 8 + c0;
            float b0 = bias ? bias[n] : 0.f;
            float b1 = bias ? bias[n + 1] : 0.f;
            float2 v0 = {acc[mi][ni][0] + b0, acc[mi][ni][1] + b1};
            float2 v1 = {acc[mi][ni][2] + b0, acc[mi][ni][3] + b1};
            *(float2*)(C + (size_t)m * N + n)       = v0;
            *(float2*)(C + (size_t)(m + 8) * N + n) = v1;
        }
    }
}

// ---------------------------------------------------------------------------
// RoPE + split (unchanged)
// ---------------------------------------------------------------------------
__global__ void rope_split(const float* __restrict__ qkv,
                           __nv_bfloat16* __restrict__ qh, __nv_bfloat16* __restrict__ ql,
                           __nv_bfloat16* __restrict__ kh, __nv_bfloat16* __restrict__ kl,
                           __nv_bfloat16* __restrict__ vh, __nv_bfloat16* __restrict__ vl)
{
    int idx = blockIdx.x * blockDim.x + threadIdx.x;
    if (idx >= B_ * S_ * H_ * 32) return;
    int j = idx & 31;
    int h = (idx >> 5) & (H_ - 1);
    int s = (idx >> 9) & (S_ - 1);
    int b = idx >> 20;

    float t   = (float)(2 * j) * (1.0f / (float)HD_);
    float inv = powf(10000.0f, -t);
    float ang = (float)s * inv;
    float cs  = cosf(ang);
    float sn  = sinf(ang);

    const float* row = qkv + ((size_t)(b * S_ + s)) * NQKV + h * HD_;
    float q1 = row[2 * j],          q2 = row[2 * j + 1];
    float k1 = row[D_ + 2 * j],     k2 = row[D_ + 2 * j + 1];
    float v1 = row[2 * D_ + 2 * j], v2 = row[2 * D_ + 2 * j + 1];

    size_t o = (((size_t)(b * H_ + h)) * S_ + s) * HD_;
    const float qs = 0.125f;
    float qa = (q1 * cs - q2 * sn) * qs;
    float qb = (q1 * sn + q2 * cs) * qs;
    float ka = k1 * cs - k2 * sn;
    float kb = k1 * sn + k2 * cs;

    __nv_bfloat16 hh, ll;
    split1(qa, hh, ll); qh[o + j] = hh;      ql[o + j] = ll;
    split1(qb, hh, ll); qh[o + 32 + j] = hh; ql[o + 32 + j] = ll;
    split1(ka, hh, ll); kh[o + j] = hh;      kl[o + j] = ll;
    split1(kb, hh, ll); kh[o + 32 + j] = hh; kl[o + 32 + j] = ll;
    uint32_t vhp, vlp;
    split_pack(v1, v2, vhp, vlp);
    *(uint32_t*)(vh + o + 2 * j) = vhp;
    *(uint32_t*)(vl + o + 2 * j) = vlp;
}

// ---------------------------------------------------------------------------
// Flash attention via mma.sync bf16x3, 2-stage cp.async KV pipeline.
// smem: Q hi/lo 32KB @0, 2 stages x 32KB (KH,KL,VH,VL each 8KB) @32KB.
// ---------------------------------------------------------------------------
#define AQ_H 0
#define AQ_L 16384
#define ASTG_BASE 32768
#define ASTG 32768
#define AK_H 0
#define AK_L 8192
#define AV_H 16384
#define AV_L 24576
#define ATT_SMEM (ASTG_BASE + 2 * ASTG)

__global__ void __launch_bounds__(256) attn_mma(
    const __nv_bfloat16* __restrict__ qh_, const __nv_bfloat16* __restrict__ ql_,
    const __nv_bfloat16* __restrict__ kh_, const __nv_bfloat16* __restrict__ kl_,
    const __nv_bfloat16* __restrict__ vh_, const __nv_bfloat16* __restrict__ vl_,
    __nv_bfloat16* __restrict__ oh_, __nv_bfloat16* __restrict__ ol_)
{
    extern __shared__ char sm[];
    const uint32_t sb = smem_u32(sm);
    const int tid  = threadIdx.x;
    const int lane = tid & 31;
    const int w    = tid >> 5;
    const int q0 = blockIdx.x * 128;
    const int h  = blockIdx.y;
    const int b  = blockIdx.z;
    const size_t bh = ((size_t)(b * H_ + h)) * S_;

    auto issue_kv = [&](int n0k, int stg) {
        uint32_t st = sb + ASTG_BASE + stg * ASTG;
#pragma unroll
        for (int it = 0; it < 2; ++it) {
            int idx = tid + it * 256;  // 64 rows x 8 chunks
            int r = idx >> 3, g = idx & 7;
            uint32_t so = r * 128 + (((uint32_t)(g ^ (r & 7))) << 4);
            size_t ga = (bh + n0k + r) * HD_ + g * 8;
            cp16(st + AK_H + so, kh_ + ga);
            cp16(st + AK_L + so, kl_ + ga);
            cp16(st + AV_H + so, vh_ + ga);
            cp16(st + AV_L + so, vl_ + ga);
        }
        CP_COMMIT();
    };

    issue_kv(0, 0);

    // stage Q tile (hi/lo) into smem, swizzled (regular stores)
#pragma unroll
    for (int it = 0; it < 4; ++it) {
        int idx = tid + it * 256;
        int r = idx >> 3, g = idx & 7;
        uint32_t so = AQ_H + r * 128 + (((uint32_t)(g ^ (r & 7))) << 4);
        size_t ga = (bh + q0 + r) * HD_ + g * 8;
        *(uint4*)(sm + so)         = *(const uint4*)(qh_ + ga);
        *(uint4*)(sm + so + 16384) = *(const uint4*)(ql_ + ga);
    }
    __syncthreads();

    uint32_t qh[4][4], ql[4][4];
    {
        const int ar = w * 16 + (lane & 7) + ((lane >> 3) & 1) * 8;
#pragma unroll
        for (int kf = 0; kf < 4; ++kf) {
            int g = kf * 2 + (lane >> 4);
            uint32_t ad = sb + AQ_H + ar * 128 + (((uint32_t)(g ^ (ar & 7))) << 4);
            ldm_x4(qh[kf], ad);
            ldm_x4(ql[kf], ad + 16384);
        }
    }

    float oacc[8][4];
    float mx[2] = {-1e30f, -1e30f};
    float li[2] = {0.f, 0.f};
#pragma unroll
    for (int dj = 0; dj < 8; ++dj)
#pragma unroll
        for (int t = 0; t < 4; ++t) oacc[dj][t] = 0.f;

    const int nkv = S_ / 64;
    for (int kc = 0; kc < nkv; ++kc) {
        if (kc + 1 < nkv) {
            issue_kv((kc + 1) * 64, (kc + 1) & 1);
            CP_WAIT(1);
        } else {
            CP_WAIT(0);
        }
        __syncthreads();
        const uint32_t st = sb + ASTG_BASE + (kc & 1) * ASTG;

        // S = Q K^T (16 x 64 per warp)
        float s[8][4];
#pragma unroll
        for (int nj = 0; nj < 8; ++nj)
#pragma unroll
            for (int t = 0; t < 4; ++t) s[nj][t] = 0.f;

#pragma unroll
        for (int ks = 0; ks < 4; ++ks) {
            const int br = ((lane >> 4) & 1) * 8 + (lane & 7);
            const int bg = ks * 2 + ((lane >> 3) & 1);
#pragma unroll
            for (int pi = 0; pi < 4; ++pi) {
                int r = br + pi * 16;
                uint32_t ad = st + AK_H + r * 128 + (((uint32_t)(bg ^ (r & 7))) << 4);
                uint32_t th[4], tl[4];
                ldm_x4(th, ad);
                ldm_x4(tl, ad + 8192);
                mma_bf16(s[pi*2],   qh[ks], th[0], th[1]);
                mma_bf16(s[pi*2],   qh[ks], tl[0], tl[1]);
                mma_bf16(s[pi*2],   ql[ks], th[0], th[1]);
                mma_bf16(s[pi*2+1], qh[ks], th[2], th[3]);
                mma_bf16(s[pi*2+1], qh[ks], tl[2], tl[3]);
                mma_bf16(s[pi*2+1], ql[ks], th[2], th[3]);
            }
        }

        // online softmax
#pragma unroll
        for (int ri = 0; ri < 2; ++ri) {
            float rm = -1e30f;
#pragma unroll
            for (int nj = 0; nj < 8; ++nj)
                rm = fmaxf(rm, fmaxf(s[nj][ri*2], s[nj][ri*2+1]));
            rm = fmaxf(rm, __shfl_xor_sync(0xffffffffu, rm, 1));
            rm = fmaxf(rm, __shfl_xor_sync(0xffffffffu, rm, 2));
            float mn   = fmaxf(mx[ri], rm);
            float corr = __expf(mx[ri] - mn);
            mx[ri] = mn;
            float rs = 0.f;
#pragma unroll
            for (int nj = 0; nj < 8; ++nj) {
                float p0 = __expf(s[nj][ri*2]   - mn);
                float p1 = __expf(s[nj][ri*2+1] - mn);
                s[nj][ri*2] = p0; s[nj][ri*2+1] = p1;
                rs += p0 + p1;
            }
            rs += __shfl_xor_sync(0xffffffffu, rs, 1);
            rs += __shfl_xor_sync(0xffffffffu, rs, 2);
            li[ri] = li[ri] * corr + rs;
#pragma unroll
            for (int dj = 0; dj < 8; ++dj) {
                oacc[dj][ri*2]   *= corr;
                oacc[dj][ri*2+1] *= corr;
            }
        }

        // O += P V
#pragma unroll
        for (int ks = 0; ks < 4; ++ks) {
            uint32_t ph[4], pl[4];
            split_pack(s[ks*2][0],   s[ks*2][1],   ph[0], pl[0]);
            split_pack(s[ks*2][2],   s[ks*2][3],   ph[1], pl[1]);
            split_pack(s[ks*2+1][0], s[ks*2+1][1], ph[2], pl[2]);
            split_pack(s[ks*2+1][2], s[ks*2+1][3], ph[3], pl[3]);

            const int vr = ks * 16 + ((lane >> 3) & 1) * 8 + (lane & 7);
#pragma unroll
            for (int pj = 0; pj < 4; ++pj) {
                int gc = pj * 2 + (lane >> 4);
                uint32_t ad = st + AV_H + vr * 128 + (((uint32_t)(gc ^ (vr & 7))) << 4);
                uint32_t th[4], tl[4];
                ldm_x4_t(th, ad);
                ldm_x4_t(tl, ad + 8192);
                mma_bf16(oacc[pj*2],   ph, th[0], th[1]);
                mma_bf16(oacc[pj*2],   ph, tl[0], tl[1]);
                mma_bf16(oacc[pj*2],   pl, th[0], th[1]);
                mma_bf16(oacc[pj*2+1], ph, th[2], th[3]);
                mma_bf16(oacc[pj*2+1], ph, tl[2], tl[3]);
                mma_bf16(oacc[pj*2+1], pl, th[2], th[3]);
            }
        }
        __syncthreads();
    }

    // epilogue
#pragma unroll
    for (int ri = 0; ri < 2; ++ri) {
        float inv = 1.0f / li[ri];
        int srow = q0 + w * 16 + (lane >> 2) + ri * 8;
        size_t rowo = ((size_t)(b * S_) + srow) * D_ + h * HD_;
#pragma unroll
        for (int dj = 0; dj < 8; ++dj) {
            int c = dj * 8 + (lane & 3) * 2;
            uint32_t hp, lp;
            split_pack(oacc[dj][ri*2] * inv, oacc[dj][ri*2+1] * inv, hp, lp);
            *(uint32_t*)(oh_ + rowo + c) = hp;
            *(uint32_t*)(ol_ + rowo + c) = lp;
        }
    }
}

// ---------------------------------------------------------------------------
extern "C" void kernel_launch(void* const* d_in, const int* in_sizes, int n_in,
                              void* d_out, int out_size)
{
    (void)in_sizes; (void)n_in; (void)out_size;
    const float* x     = (const float*)d_in[0];
    const float* w_qkv = (const float*)d_in[1];
    const float* w_out = (const float*)d_in[2];
    const float* b_out = (const float*)d_in[3];
    float* out = (float*)d_out;

    float* p_qkv;
    cudaGetSymbolAddress((void**)&p_qkv, g_qkv);
    __nv_bfloat16 *xh, *xl, *wqh, *wql, *woh, *wol;
    __nv_bfloat16 *qh, *ql, *kh, *kl, *vh, *vl, *oh, *ol;
    cudaGetSymbolAddress((void**)&xh,  g_xh);
    cudaGetSymbolAddress((void**)&xl,  g_xl);
    cudaGetSymbolAddress((void**)&wqh, g_wqh);
    cudaGetSymbolAddress((void**)&wql, g_wql);
    cudaGetSymbolAddress((void**)&woh, g_woh);
    cudaGetSymbolAddress((void**)&wol, g_wol);
    cudaGetSymbolAddress((void**)&qh,  g_qhb);
    cudaGetSymbolAddress((void**)&ql,  g_qlb);
    cudaGetSymbolAddress((void**)&kh,  g_khb);
    cudaGetSymbolAddress((void**)&kl,  g_klb);
    cudaGetSymbolAddress((void**)&vh,  g_vhb);
    cudaGetSymbolAddress((void**)&vl,  g_vlb);
    cudaGetSymbolAddress((void**)&oh,  g_ohb);
    cudaGetSymbolAddress((void**)&ol,  g_olb);

    cudaFuncSetAttribute(gemm_mma,
        cudaFuncAttributeMaxDynamicSharedMemorySize, GEMM_SMEM);
    cudaFuncSetAttribute(attn_mma,
        cudaFuncAttributeMaxDynamicSharedMemorySize, ATT_SMEM);

    {
        int n4;
        n4 = (M_ * D_) / 4;
        split_bf16<<<(n4 + 255) / 256, 256>>>(x, xh, xl, n4);
        n4 = (NQKV * D_) / 4;
        split_bf16<<<(n4 + 255) / 256, 256>>>(w_qkv, wqh, wql, n4);
        n4 = (D_ * D_) / 4;
        split_bf16<<<(n4 + 255) / 256, 256>>>(w_out, woh, wol, n4);
    }
    {
        dim3 grid(NQKV / 128, M_ / 128);
        gemm_mma<<<grid, 256, GEMM_SMEM>>>(xh, xl, wqh, wql, nullptr, p_qkv,
                                           M_, NQKV, D_);
    }
    {
        int total = B_ * S_ * H_ * 32;
        rope_split<<<(total + 255) / 256, 256>>>(p_qkv, qh, ql, kh, kl, vh, vl);
    }
    {
        dim3 grid(S_ / 128, H_, B_);
        attn_mma<<<grid, 256, ATT_SMEM>>>(qh, ql, kh, kl, vh, vl, oh, ol);
    }
    {
        dim3 grid(D_ / 128, M_ / 128);
        gemm_mma<<<grid, 256, GEMM_SMEM>>>(oh, ol, woh, wol, b_out, out,
                                           M_, D_, D_);
    }
}

// round 5
// speedup vs baseline: 3.5253x; 1.1478x over previous
#include <cuda_runtime.h>
#include <cuda_bf16.h>
#include <math.h>
#include <cstdint>

#define B_   2
#define S_   2048
#define D_   1024
#define H_   16
#define HD_  64
#define M_   (B_ * S_)      // 4096
#define NQKV (3 * D_)       // 3072

// ---------------- scratch (static device globals; no allocation) ----------
__device__ float g_qkv[(size_t)M_ * NQKV];      // fp32 [B*S, 3D] (natural)
__device__ float g_x32[(size_t)M_ * D_];        // tf32-rounded, k-permuted
__device__ float g_wq32[(size_t)NQKV * D_];
__device__ float g_wo32[(size_t)D_ * D_];
__device__ float g_q32[(size_t)M_ * D_];        // [B,H,S,perm(d)]
__device__ float g_k32[(size_t)M_ * D_];        // [B,H,S,perm(d)]
__device__ float g_vT32[(size_t)M_ * D_];       // [B,H,d,perm_s(S)]
__device__ float g_o32[(size_t)M_ * D_];        // [B*S, perm(D)]

// =====================  helpers  ===========================================
__device__ __forceinline__ uint32_t smem_u32(const void* p) {
    uint32_t a;
    asm("{ .reg .u64 t; cvta.to.shared.u64 t, %1; cvt.u32.u64 %0, t; }"
        : "=r"(a) : "l"(p));
    return a;
}
__device__ __forceinline__ float rna_tf32(float x) {
    uint32_t u;
    asm("cvt.rna.tf32.f32 %0, %1;" : "=r"(u) : "f"(x));
    return __uint_as_float(u);
}
__device__ __forceinline__ void mma_tf32(float (&d)[4], const uint32_t (&a)[4],
                                         uint32_t b0, uint32_t b1) {
    asm volatile(
        "mma.sync.aligned.m16n8k8.row.col.f32.tf32.tf32.f32 "
        "{%0,%1,%2,%3}, {%4,%5,%6,%7}, {%8,%9}, {%0,%1,%2,%3};"
        : "+f"(d[0]), "+f"(d[1]), "+f"(d[2]), "+f"(d[3])
        : "r"(a[0]), "r"(a[1]), "r"(a[2]), "r"(a[3]), "r"(b0), "r"(b1));
}
__device__ __forceinline__ void cp16(uint32_t saddr, const void* gaddr) {
    asm volatile("cp.async.cg.shared.global [%0], [%1], 16;"
        :: "r"(saddr), "l"(gaddr));
}
#define CP_COMMIT() asm volatile("cp.async.commit_group;" ::: "memory")
#define CP_WAIT(n)  asm volatile("cp.async.wait_group %0;" :: "n"(n) : "memory")

// frag permutation: within each 8-group, (t, t+4) become adjacent (2t, 2t+1)
__host__ __device__ __forceinline__ int perm8(int x) {
    return ((x & 3) << 1) | ((x >> 2) & 1);
}
__host__ __device__ __forceinline__ int permk(int k) {
    return (k & ~7) | perm8(k & 7);
}

// ---------------------------------------------------------------------------
// cvt + permute: dst[r][perm(c)] = rna_tf32(src[r][c])
// ---------------------------------------------------------------------------
__global__ void cvt_perm(const float* __restrict__ src, float* __restrict__ dst,
                         int n, int cols)
{
    int i = blockIdx.x * blockDim.x + threadIdx.x;
    if (i >= n) return;
    int r = i / cols, c = i % cols;
    dst[(size_t)r * cols + permk(c)] = rna_tf32(src[i]);
}

// ---------------------------------------------------------------------------
// GEMM (NT) tf32: C[m,n] = sum_k A[m,k]*B[n,k] (+bias)
// A,B pre-rounded + k-permuted. CTA 128x128, K-chunk 32, 2-stage cp.async.
// 8 warps, warp tile 64x32. smem row stride 40 floats (conflict-free).
// ---------------------------------------------------------------------------
#define G_SROW 160                 // bytes per smem row (32 floats + pad)
#define G_AOFF 0
#define G_BOFF (128 * G_SROW)      // 20480
#define G_STG  (2 * 128 * G_SROW)  // 40960
#define GEMM_SMEM (2 * G_STG)      // 81920

__global__ void __launch_bounds__(256, 2) gemm_tf32(
    const float* __restrict__ A, const float* __restrict__ Bw,
    const float* __restrict__ bias, float* __restrict__ C,
    int M, int N, int K)
{
    extern __shared__ char sm[];
    const uint32_t sb = smem_u32(sm);
    const int tid  = threadIdx.x;
    const int lane = tid & 31;
    const int w    = tid >> 5;
    const int g    = lane >> 2;
    const int t    = lane & 3;
    const int m0 = blockIdx.y * 128;
    const int n0 = blockIdx.x * 128;
    const int wm = (w & 1) * 64;
    const int wn = (w >> 1) * 32;

    float acc[4][4][4];
#pragma unroll
    for (int mi = 0; mi < 4; ++mi)
#pragma unroll
        for (int ni = 0; ni < 4; ++ni)
#pragma unroll
            for (int q = 0; q < 4; ++q) acc[mi][ni][q] = 0.f;

    const int nch = K >> 5;

    auto issue = [&](int kc, int stg) {
        uint32_t st = sb + stg * G_STG;
#pragma unroll
        for (int it = 0; it < 4; ++it) {
            int idx = tid + it * 256;        // 1024: 128 rows x 8 x 16B
            int r = idx >> 3, c = idx & 7;
            cp16(st + G_AOFF + r * G_SROW + c * 16,
                 A + (size_t)(m0 + r) * K + kc * 32 + c * 4);
            cp16(st + G_BOFF + r * G_SROW + c * 16,
                 Bw + (size_t)(n0 + r) * K + kc * 32 + c * 4);
        }
        CP_COMMIT();
    };

    issue(0, 0);

    for (int kc = 0; kc < nch; ++kc) {
        if (kc + 1 < nch) { issue(kc + 1, (kc + 1) & 1); CP_WAIT(1); }
        else             { CP_WAIT(0); }
        __syncthreads();
        const uint32_t st = sb + (kc & 1) * G_STG;

#pragma unroll
        for (int ks = 0; ks < 4; ++ks) {
            uint32_t a[4][4];
#pragma unroll
            for (int mi = 0; mi < 4; ++mi) {
                int r = wm + mi * 16 + g;
                float2 v0 = *(float2*)(sm + (kc & 1) * G_STG + G_AOFF +
                                       r * G_SROW + ks * 32 + t * 8);
                float2 v1 = *(float2*)(sm + (kc & 1) * G_STG + G_AOFF +
                                       (r + 8) * G_SROW + ks * 32 + t * 8);
                a[mi][0] = __float_as_uint(v0.x);
                a[mi][1] = __float_as_uint(v1.x);
                a[mi][2] = __float_as_uint(v0.y);
                a[mi][3] = __float_as_uint(v1.y);
            }
            uint32_t b[4][2];
#pragma unroll
            for (int ni = 0; ni < 4; ++ni) {
                int r = wn + ni * 8 + g;
                float2 v = *(float2*)(sm + (kc & 1) * G_STG + G_BOFF +
                                      r * G_SROW + ks * 32 + t * 8);
                b[ni][0] = __float_as_uint(v.x);
                b[ni][1] = __float_as_uint(v.y);
            }
#pragma unroll
            for (int mi = 0; mi < 4; ++mi)
#pragma unroll
                for (int ni = 0; ni < 4; ++ni)
                    mma_tf32(acc[mi][ni], a[mi], b[ni][0], b[ni][1]);
        }
        __syncthreads();
        (void)st;
    }

    const int c0 = t * 2;
#pragma unroll
    for (int mi = 0; mi < 4; ++mi) {
#pragma unroll
        for (int ni = 0; ni < 4; ++ni) {
            int m = m0 + wm + mi * 16 + g;
            int n = n0 + wn + ni * 8 + c0;
            float b0 = bias ? bias[n] : 0.f;
            float b1 = bias ? bias[n + 1] : 0.f;
            float2 v0 = {acc[mi][ni][0] + b0, acc[mi][ni][1] + b1};
            float2 v1 = {acc[mi][ni][2] + b0, acc[mi][ni][3] + b1};
            *(float2*)(C + (size_t)m * N + n)       = v0;
            *(float2*)(C + (size_t)(m + 8) * N + n) = v1;
        }
    }
}

// ---------------------------------------------------------------------------
// RoPE: fp32 qkv -> tf32-rounded q/k [B,H,S,perm(d)], v^T [B,H,d,perm_s(s)].
// Q pre-scaled by 1/sqrt(64).
// ---------------------------------------------------------------------------
__global__ void rope_tf32(const float* __restrict__ qkv,
                          float* __restrict__ q32, float* __restrict__ k32,
                          float* __restrict__ vT)
{
    int idx = blockIdx.x * blockDim.x + threadIdx.x;
    if (idx >= B_ * S_ * H_ * 32) return;
    int j = idx & 31;
    int h = (idx >> 5) & (H_ - 1);
    int s = (idx >> 9) & (S_ - 1);
    int b = idx >> 20;

    float tt  = (float)(2 * j) * (1.0f / (float)HD_);
    float inv = powf(10000.0f, -tt);
    float ang = (float)s * inv;
    float cs  = cosf(ang);
    float sn  = sinf(ang);

    const float* row = qkv + ((size_t)(b * S_ + s)) * NQKV + h * HD_;
    float q1 = row[2 * j],          q2 = row[2 * j + 1];
    float k1 = row[D_ + 2 * j],     k2 = row[D_ + 2 * j + 1];
    float v1 = row[2 * D_ + 2 * j], v2 = row[2 * D_ + 2 * j + 1];

    size_t o = (((size_t)(b * H_ + h)) * S_ + s) * HD_;
    const float qs = 0.125f;
    q32[o + permk(j)]      = rna_tf32((q1 * cs - q2 * sn) * qs);
    q32[o + permk(j + 32)] = rna_tf32((q1 * sn + q2 * cs) * qs);
    k32[o + permk(j)]      = rna_tf32(k1 * cs - k2 * sn);
    k32[o + permk(j + 32)] = rna_tf32(k1 * sn + k2 * cs);

    int sp = (s & ~7) | perm8(s & 7);
    size_t bh64 = ((size_t)(b * H_ + h)) * HD_;
    vT[(bh64 + 2 * j)     * S_ + sp] = rna_tf32(v1);
    vT[(bh64 + 2 * j + 1) * S_ + sp] = rna_tf32(v2);
}

// ---------------------------------------------------------------------------
// Flash attention, tf32 mma. CTA 256 thr (8 warps), q-tile 128 (16/warp),
// kv-tile 64, 2-stage cp.async. Q staged in stage0 region then regs.
// smem rows: 64 floats + pad -> stride 72 floats (288B).
// ---------------------------------------------------------------------------
#define A_SROW 288
#define A_KOFF 0
#define A_VOFF (64 * A_SROW)       // 18432
#define A_STG  (128 * A_SROW)      // 36864
#define ATT_SMEM (2 * A_STG)       // 73728

__global__ void __launch_bounds__(256, 2) attn_tf32(
    const float* __restrict__ q_, const float* __restrict__ k_,
    const float* __restrict__ vT_, float* __restrict__ o_)
{
    extern __shared__ char sm[];
    const uint32_t sb = smem_u32(sm);
    const int tid  = threadIdx.x;
    const int lane = tid & 31;
    const int w    = tid >> 5;
    const int g    = lane >> 2;
    const int t    = lane & 3;
    const int q0 = blockIdx.x * 128;
    const int h  = blockIdx.y;
    const int b  = blockIdx.z;
    const size_t bh   = ((size_t)(b * H_ + h)) * S_;
    const size_t bh64 = ((size_t)(b * H_ + h)) * HD_;

    // --- stage Q (128 rows x 256B) into stage0 region, extract frags ---
#pragma unroll
    for (int it = 0; it < 8; ++it) {
        int idx = tid + it * 256;          // 2048: 128 rows x 16 x 16B
        int r = idx >> 4, c = idx & 15;
        cp16(sb + r * A_SROW + c * 16, q_ + (bh + q0 + r) * HD_ + c * 4);
    }
    CP_COMMIT();
    CP_WAIT(0);
    __syncthreads();

    uint32_t qf[8][4];
#pragma unroll
    for (int ks = 0; ks < 8; ++ks) {
        int r = w * 16 + g;
        float2 v0 = *(float2*)(sm + r * A_SROW + ks * 32 + t * 8);
        float2 v1 = *(float2*)(sm + (r + 8) * A_SROW + ks * 32 + t * 8);
        qf[ks][0] = __float_as_uint(v0.x);
        qf[ks][1] = __float_as_uint(v1.x);
        qf[ks][2] = __float_as_uint(v0.y);
        qf[ks][3] = __float_as_uint(v1.y);
    }
    __syncthreads();   // everyone done reading Q region

    auto issue_kv = [&](int n0k, int stg) {
        uint32_t st = sb + stg * A_STG;
#pragma unroll
        for (int it = 0; it < 8; ++it) {
            int idx = tid + it * 256;      // 2048 total: 1024 K + 1024 V
            int half = idx >> 10;          // 0 = K, 1 = V
            int loc = idx & 1023;
            int r = loc >> 4, c = loc & 15;
            if (half == 0)
                cp16(st + A_KOFF + r * A_SROW + c * 16,
                     k_ + (bh + n0k + r) * HD_ + c * 4);
            else
                cp16(st + A_VOFF + r * A_SROW + c * 16,
                     vT_ + (bh64 + r) * S_ + n0k + c * 4);
        }
        CP_COMMIT();
    };

    issue_kv(0, 0);

    float oacc[8][4];
    float mx[2] = {-1e30f, -1e30f};
    float li[2] = {0.f, 0.f};
#pragma unroll
    for (int dj = 0; dj < 8; ++dj)
#pragma unroll
        for (int q = 0; q < 4; ++q) oacc[dj][q] = 0.f;

    const int src0 = (lane & ~3) | (t >> 1);
    const int src1 = src0 + 2;

    const int nkv = S_ / 64;
    for (int kc = 0; kc < nkv; ++kc) {
        if (kc + 1 < nkv) { issue_kv((kc + 1) * 64, (kc + 1) & 1); CP_WAIT(1); }
        else              { CP_WAIT(0); }
        __syncthreads();
        char* st = sm + (kc & 1) * A_STG;

        // ---- S = Q K^T (16 x 64 per warp) ----
        float s[8][4];
#pragma unroll
        for (int nj = 0; nj < 8; ++nj)
#pragma unroll
            for (int q = 0; q < 4; ++q) s[nj][q] = 0.f;

#pragma unroll
        for (int ks = 0; ks < 8; ++ks) {
#pragma unroll
            for (int nj = 0; nj < 8; ++nj) {
                float2 v = *(float2*)(st + A_KOFF + (nj * 8 + g) * A_SROW +
                                      ks * 32 + t * 8);
                mma_tf32(s[nj], qf[ks], __float_as_uint(v.x),
                         __float_as_uint(v.y));
            }
        }

        // ---- online softmax ----
#pragma unroll
        for (int ri = 0; ri < 2; ++ri) {
            float rm = -1e30f;
#pragma unroll
            for (int nj = 0; nj < 8; ++nj)
                rm = fmaxf(rm, fmaxf(s[nj][ri*2], s[nj][ri*2+1]));
            rm = fmaxf(rm, __shfl_xor_sync(0xffffffffu, rm, 1));
            rm = fmaxf(rm, __shfl_xor_sync(0xffffffffu, rm, 2));
            float mn   = fmaxf(mx[ri], rm);
            float corr = __expf(mx[ri] - mn);
            mx[ri] = mn;
            float rs = 0.f;
#pragma unroll
            for (int nj = 0; nj < 8; ++nj) {
                float p0 = __expf(s[nj][ri*2]   - mn);
                float p1 = __expf(s[nj][ri*2+1] - mn);
                s[nj][ri*2] = p0; s[nj][ri*2+1] = p1;
                rs += p0 + p1;
            }
            rs += __shfl_xor_sync(0xffffffffu, rs, 1);
            rs += __shfl_xor_sync(0xffffffffu, rs, 2);
            li[ri] = li[ri] * corr + rs;
#pragma unroll
            for (int dj = 0; dj < 8; ++dj) {
                oacc[dj][ri*2]   *= corr;
                oacc[dj][ri*2+1] *= corr;
            }
        }

        // ---- O += P V : build P A-frag via shfl permutation ----
#pragma unroll
        for (int kk = 0; kk < 8; ++kk) {
            float y00 = __shfl_sync(0xffffffffu, s[kk][0], src0);
            float y01 = __shfl_sync(0xffffffffu, s[kk][1], src0);
            float y10 = __shfl_sync(0xffffffffu, s[kk][0], src1);
            float y11 = __shfl_sync(0xffffffffu, s[kk][1], src1);
            float y20 = __shfl_sync(0xffffffffu, s[kk][2], src0);
            float y21 = __shfl_sync(0xffffffffu, s[kk][3], src0);
            float y30 = __shfl_sync(0xffffffffu, s[kk][2], src1);
            float y31 = __shfl_sync(0xffffffffu, s[kk][3], src1);
            uint32_t pa[4];
            pa[0] = __float_as_uint(rna_tf32((t & 1) ? y01 : y00));
            pa[1] = __float_as_uint(rna_tf32((t & 1) ? y21 : y20));
            pa[2] = __float_as_uint(rna_tf32((t & 1) ? y11 : y10));
            pa[3] = __float_as_uint(rna_tf32((t & 1) ? y31 : y30));
#pragma unroll
            for (int dj = 0; dj < 8; ++dj) {
                float2 v = *(float2*)(st + A_VOFF + (dj * 8 + g) * A_SROW +
                                      kk * 32 + t * 8);
                mma_tf32(oacc[dj], pa, __float_as_uint(v.x),
                         __float_as_uint(v.y));
            }
        }
        __syncthreads();
    }

    // ---- epilogue: normalize, round, write k-permuted [B*S, perm(D)] ----
#pragma unroll
    for (int ri = 0; ri < 2; ++ri) {
        float inv = 1.0f / li[ri];
        int srow = q0 + w * 16 + g + ri * 8;
        size_t rowo = ((size_t)(b * S_) + srow) * D_ + h * HD_;
#pragma unroll
        for (int dj = 0; dj < 8; ++dj) {
            int c = dj * 8 + 2 * t;
            o_[rowo + permk(c)]     = rna_tf32(oacc[dj][ri*2]   * inv);
            o_[rowo + permk(c + 1)] = rna_tf32(oacc[dj][ri*2+1] * inv);
        }
    }
}

// ---------------------------------------------------------------------------
extern "C" void kernel_launch(void* const* d_in, const int* in_sizes, int n_in,
                              void* d_out, int out_size)
{
    (void)in_sizes; (void)n_in; (void)out_size;
    const float* x     = (const float*)d_in[0];
    const float* w_qkv = (const float*)d_in[1];
    const float* w_out = (const float*)d_in[2];
    const float* b_out = (const float*)d_in[3];
    float* out = (float*)d_out;

    float *p_qkv, *p_x, *p_wq, *p_wo, *p_q, *p_k, *p_vT, *p_o;
    cudaGetSymbolAddress((void**)&p_qkv, g_qkv);
    cudaGetSymbolAddress((void**)&p_x,   g_x32);
    cudaGetSymbolAddress((void**)&p_wq,  g_wq32);
    cudaGetSymbolAddress((void**)&p_wo,  g_wo32);
    cudaGetSymbolAddress((void**)&p_q,   g_q32);
    cudaGetSymbolAddress((void**)&p_k,   g_k32);
    cudaGetSymbolAddress((void**)&p_vT,  g_vT32);
    cudaGetSymbolAddress((void**)&p_o,   g_o32);

    cudaFuncSetAttribute(gemm_tf32,
        cudaFuncAttributeMaxDynamicSharedMemorySize, GEMM_SMEM);
    cudaFuncSetAttribute(attn_tf32,
        cudaFuncAttributeMaxDynamicSharedMemorySize, ATT_SMEM);

    // 0) round+permute inputs / weights
    {
        int n;
        n = M_ * D_;
        cvt_perm<<<(n + 255) / 256, 256>>>(x, p_x, n, D_);
        n = NQKV * D_;
        cvt_perm<<<(n + 255) / 256, 256>>>(w_qkv, p_wq, n, D_);
        n = D_ * D_;
        cvt_perm<<<(n + 255) / 256, 256>>>(w_out, p_wo, n, D_);
    }
    // 1) QKV projection
    {
        dim3 grid(NQKV / 128, M_ / 128);
        gemm_tf32<<<grid, 256, GEMM_SMEM>>>(p_x, p_wq, nullptr, p_qkv,
                                            M_, NQKV, D_);
    }
    // 2) RoPE -> tf32 q/k/vT
    {
        int total = B_ * S_ * H_ * 32;
        rope_tf32<<<(total + 255) / 256, 256>>>(p_qkv, p_q, p_k, p_vT);
    }
    // 3) flash attention
    {
        dim3 grid(S_ / 128, H_, B_);
        attn_tf32<<<grid, 256, ATT_SMEM>>>(p_q, p_k, p_vT, p_o);
    }
    // 4) output projection + bias
    {
        dim3 grid(D_ / 128, M_ / 128);
        gemm_tf32<<<grid, 256, GEMM_SMEM>>>(p_o, p_wo, b_out, out,
                                            M_, D_, D_);
    }
}

// round 6
// speedup vs baseline: 3.5563x; 1.0088x over previous
#include <cuda_runtime.h>
#include <cuda_bf16.h>
#include <math.h>
#include <cstdint>

#define B_   2
#define S_   2048
#define D_   1024
#define H_   16
#define HD_  64
#define M_   (B_ * S_)      // 4096
#define NQKV (3 * D_)       // 3072

// ---------------- scratch (static device globals; no allocation) ----------
__device__ float g_qkv[(size_t)M_ * NQKV];      // fp32 [B*S, 3D] (natural)
__device__ float g_x32[(size_t)M_ * D_];        // tf32-rounded, k16-permuted
__device__ float g_wq32[(size_t)NQKV * D_];
__device__ float g_wo32[(size_t)D_ * D_];
__device__ float g_q32[(size_t)M_ * D_];        // [B,H,S,perm16(d)]
__device__ float g_k32[(size_t)M_ * D_];        // [B,H,S,perm16(d)]
__device__ float g_vT32[(size_t)M_ * D_];       // [B,H,d,perm16_s(S)]
__device__ float g_o32[(size_t)M_ * D_];        // [B*S, perm16(D)]

// =====================  helpers  ===========================================
__device__ __forceinline__ uint32_t smem_u32(const void* p) {
    uint32_t a;
    asm("{ .reg .u64 t; cvta.to.shared.u64 t, %1; cvt.u32.u64 %0, t; }"
        : "=r"(a) : "l"(p));
    return a;
}
__device__ __forceinline__ float rna_tf32(float x) {
    uint32_t u;
    asm("cvt.rna.tf32.f32 %0, %1;" : "=r"(u) : "f"(x));
    return __uint_as_float(u);
}
__device__ __forceinline__ void mma_tf32(float (&d)[4], const uint32_t (&a)[4],
                                         uint32_t b0, uint32_t b1) {
    asm volatile(
        "mma.sync.aligned.m16n8k8.row.col.f32.tf32.tf32.f32 "
        "{%0,%1,%2,%3}, {%4,%5,%6,%7}, {%8,%9}, {%0,%1,%2,%3};"
        : "+f"(d[0]), "+f"(d[1]), "+f"(d[2]), "+f"(d[3])
        : "r"(a[0]), "r"(a[1]), "r"(a[2]), "r"(a[3]), "r"(b0), "r"(b1));
}
__device__ __forceinline__ void cp16(uint32_t saddr, const void* gaddr) {
    asm volatile("cp.async.cg.shared.global [%0], [%1], 16;"
        :: "r"(saddr), "l"(gaddr));
}
#define CP_COMMIT() asm volatile("cp.async.commit_group;" ::: "memory")
#define CP_WAIT(n)  asm volatile("cp.async.wait_group %0;" :: "n"(n) : "memory")

// 16-wide k permutation: thread t's 4 values for 2 k-steps become one float4
__host__ __device__ __forceinline__ int p16(int u) {
    return ((u & 3) << 2) | ((u >> 2) & 3);
}
__host__ __device__ __forceinline__ int permk16(int k) {
    return (k & ~15) | p16(k & 15);
}

// ---------------------------------------------------------------------------
// cvt + permute (vectorized x4): dst[r][permk16(c)] = rna_tf32(src[r][c])
// ---------------------------------------------------------------------------
__global__ void cvt_perm4(const float* __restrict__ src, float* __restrict__ dst,
                          int n4, int cols)
{
    int i = blockIdx.x * blockDim.x + threadIdx.x;
    if (i >= n4) return;
    int cols4 = cols >> 2;
    int r  = i / cols4;
    int cq = i - r * cols4;            // quad index within row
    float4 v = ((const float4*)src)[i];
    int q      = cq & 3;
    int base16 = (cq >> 2) << 4;
    float* drow = dst + (size_t)r * cols + base16 + q;
    drow[0]  = rna_tf32(v.x);
    drow[4]  = rna_tf32(v.y);
    drow[8]  = rna_tf32(v.z);
    drow[12] = rna_tf32(v.w);
}

// ---------------------------------------------------------------------------
// GEMM (NT) tf32: C[m,n] = sum_k A[m,k]*B[n,k] (+bias)
// A,B pre-rounded + k16-permuted. CTA 128x128, K-chunk 32, 3-stage cp.async.
// smem rows 128B exact, parity XOR swizzle on 16B chunks. 8 warps, 64x32 each.
// ---------------------------------------------------------------------------
#define G_BOFF 16384               // B tile offset within stage
#define G_STG  32768               // 2 x (128 rows x 128B)
#define GEMM_SMEM (3 * G_STG)      // 98304

__global__ void __launch_bounds__(256, 2) gemm_tf32(
    const float* __restrict__ A, const float* __restrict__ Bw,
    const float* __restrict__ bias, float* __restrict__ C,
    int M, int N, int K)
{
    extern __shared__ char sm[];
    const int tid  = threadIdx.x;
    const int lane = tid & 31;
    const int w    = tid >> 5;
    const int g    = lane >> 2;
    const int t    = lane & 3;
    const int m0 = blockIdx.y * 128;
    const int n0 = blockIdx.x * 128;
    const int wm = (w & 1) * 64;
    const int wn = (w >> 1) * 32;

    float acc[4][4][4];
#pragma unroll
    for (int mi = 0; mi < 4; ++mi)
#pragma unroll
        for (int ni = 0; ni < 4; ++ni)
#pragma unroll
            for (int q = 0; q < 4; ++q) acc[mi][ni][q] = 0.f;

    const int nch = K >> 5;
    const uint32_t sb = smem_u32(sm);

    auto issue = [&](int kc, int stg) {
        uint32_t st = sb + stg * G_STG;
#pragma unroll
        for (int it = 0; it < 4; ++it) {
            int idx = tid + it * 256;        // 1024: 128 rows x 8 chunks
            int r = idx >> 3, c = idx & 7;
            uint32_t so = r * 128 + (((uint32_t)(c ^ ((r & 1) << 2))) << 4);
            cp16(st + so,          A  + (size_t)(m0 + r) * K + kc * 32 + c * 4);
            cp16(st + G_BOFF + so, Bw + (size_t)(n0 + r) * K + kc * 32 + c * 4);
        }
        CP_COMMIT();
    };

    issue(0, 0);
    if (nch > 1) issue(1, 1);

    for (int kc = 0; kc < nch; ++kc) {
        if (kc + 2 < nch) { issue(kc + 2, (kc + 2) % 3); CP_WAIT(2); }
        else if (kc + 1 < nch) { CP_WAIT(1); }
        else { CP_WAIT(0); }
        __syncthreads();
        char* st = sm + (kc % 3) * G_STG;

#pragma unroll
        for (int ks2 = 0; ks2 < 2; ++ks2) {
            // B fragments: one float4 per ni covers 2 k-steps
            float4 bf[4];
#pragma unroll
            for (int ni = 0; ni < 4; ++ni) {
                int r = wn + ni * 8 + g;
                int c = (ks2 * 4 + t) ^ ((r & 1) << 2);
                bf[ni] = *(float4*)(st + G_BOFF + r * 128 + c * 16);
            }
#pragma unroll
            for (int mi = 0; mi < 4; ++mi) {
                int r0 = wm + mi * 16 + g;
                int c  = (ks2 * 4 + t) ^ ((r0 & 1) << 2);
                float4 lo = *(float4*)(st + r0 * 128 + c * 16);
                float4 hi = *(float4*)(st + (r0 + 8) * 128 + c * 16);
                uint32_t ae[4] = {__float_as_uint(lo.x), __float_as_uint(hi.x),
                                  __float_as_uint(lo.y), __float_as_uint(hi.y)};
                uint32_t ao[4] = {__float_as_uint(lo.z), __float_as_uint(hi.z),
                                  __float_as_uint(lo.w), __float_as_uint(hi.w)};
#pragma unroll
                for (int ni = 0; ni < 4; ++ni) {
                    mma_tf32(acc[mi][ni], ae, __float_as_uint(bf[ni].x),
                             __float_as_uint(bf[ni].y));
                    mma_tf32(acc[mi][ni], ao, __float_as_uint(bf[ni].z),
                             __float_as_uint(bf[ni].w));
                }
            }
        }
        __syncthreads();
    }

    const int c0 = t * 2;
#pragma unroll
    for (int mi = 0; mi < 4; ++mi) {
#pragma unroll
        for (int ni = 0; ni < 4; ++ni) {
            int m = m0 + wm + mi * 16 + g;
            int n = n0 + wn + ni * 8 + c0;
            float b0 = bias ? bias[n] : 0.f;
            float b1 = bias ? bias[n + 1] : 0.f;
            float2 v0 = {acc[mi][ni][0] + b0, acc[mi][ni][1] + b1};
            float2 v1 = {acc[mi][ni][2] + b0, acc[mi][ni][3] + b1};
            *(float2*)(C + (size_t)m * N + n)       = v0;
            *(float2*)(C + (size_t)(m + 8) * N + n) = v1;
        }
    }
}

// ---------------------------------------------------------------------------
// RoPE: fp32 qkv -> tf32 q/k [B,H,S,perm16(d)], v^T [B,H,d,perm16(s)].
// Q pre-scaled by 1/sqrt(64).
// ---------------------------------------------------------------------------
__global__ void rope_tf32(const float* __restrict__ qkv,
                          float* __restrict__ q32, float* __restrict__ k32,
                          float* __restrict__ vT)
{
    int idx = blockIdx.x * blockDim.x + threadIdx.x;
    if (idx >= B_ * S_ * H_ * 32) return;
    int j = idx & 31;
    int h = (idx >> 5) & (H_ - 1);
    int s = (idx >> 9) & (S_ - 1);
    int b = idx >> 20;

    float tt  = (float)(2 * j) * (1.0f / (float)HD_);
    float inv = powf(10000.0f, -tt);
    float ang = (float)s * inv;
    float cs, sn;
    sincosf(ang, &sn, &cs);

    const float* row = qkv + ((size_t)(b * S_ + s)) * NQKV + h * HD_;
    float q1 = row[2 * j],          q2 = row[2 * j + 1];
    float k1 = row[D_ + 2 * j],     k2 = row[D_ + 2 * j + 1];
    float v1 = row[2 * D_ + 2 * j], v2 = row[2 * D_ + 2 * j + 1];

    size_t o = (((size_t)(b * H_ + h)) * S_ + s) * HD_;
    const float qs = 0.125f;
    q32[o + permk16(j)]      = rna_tf32((q1 * cs - q2 * sn) * qs);
    q32[o + permk16(j + 32)] = rna_tf32((q1 * sn + q2 * cs) * qs);
    k32[o + permk16(j)]      = rna_tf32(k1 * cs - k2 * sn);
    k32[o + permk16(j + 32)] = rna_tf32(k1 * sn + k2 * cs);

    int sp = (s & ~15) | p16(s & 15);
    size_t bh64 = ((size_t)(b * H_ + h)) * HD_;
    vT[(bh64 + 2 * j)     * S_ + sp] = rna_tf32(v1);
    vT[(bh64 + 2 * j + 1) * S_ + sp] = rna_tf32(v2);
}

// ---------------------------------------------------------------------------
// Flash attention, tf32 mma. 8 warps, q-tile 128 (16/warp), kv-tile 64,
// 2-stage cp.async. Rows 256B exact + parity chunk swizzle.
// stage = K tile (16KB) + V tile (16KB); Q staged in stage0 before loop.
// ---------------------------------------------------------------------------
#define A_VOFF 16384
#define A_STG  32768
#define ATT_SMEM (2 * A_STG)       // 65536

__global__ void __launch_bounds__(256, 2) attn_tf32(
    const float* __restrict__ q_, const float* __restrict__ k_,
    const float* __restrict__ vT_, float* __restrict__ o_)
{
    extern __shared__ char sm[];
    const uint32_t sb = smem_u32(sm);
    const int tid  = threadIdx.x;
    const int lane = tid & 31;
    const int w    = tid >> 5;
    const int g    = lane >> 2;
    const int t    = lane & 3;
    const int q0 = blockIdx.x * 128;
    const int h  = blockIdx.y;
    const int b  = blockIdx.z;
    const size_t bh   = ((size_t)(b * H_ + h)) * S_;
    const size_t bh64 = ((size_t)(b * H_ + h)) * HD_;

    // --- stage Q (128 rows x 256B) into stage0 region, extract frags ---
#pragma unroll
    for (int it = 0; it < 8; ++it) {
        int idx = tid + it * 256;          // 2048: 128 rows x 16 chunks
        int r = idx >> 4, c = idx & 15;
        uint32_t so = r * 256 + (((uint32_t)(c ^ ((r & 1) << 2))) << 4);
        cp16(sb + so, q_ + (bh + q0 + r) * HD_ + c * 4);
    }
    CP_COMMIT();
    CP_WAIT(0);
    __syncthreads();

    uint32_t qf[8][4];
    {
        int r0 = w * 16 + g;
#pragma unroll
        for (int ks2 = 0; ks2 < 4; ++ks2) {
            int c = (ks2 * 4 + t) ^ ((r0 & 1) << 2);
            float4 lo = *(float4*)(sm + r0 * 256 + c * 16);
            float4 hi = *(float4*)(sm + (r0 + 8) * 256 + c * 16);
            qf[ks2*2][0]   = __float_as_uint(lo.x);
            qf[ks2*2][1]   = __float_as_uint(hi.x);
            qf[ks2*2][2]   = __float_as_uint(lo.y);
            qf[ks2*2][3]   = __float_as_uint(hi.y);
            qf[ks2*2+1][0] = __float_as_uint(lo.z);
            qf[ks2*2+1][1] = __float_as_uint(hi.z);
            qf[ks2*2+1][2] = __float_as_uint(lo.w);
            qf[ks2*2+1][3] = __float_as_uint(hi.w);
        }
    }
    __syncthreads();   // everyone done reading Q region

    auto issue_kv = [&](int n0k, int stg) {
        uint32_t st = sb + stg * A_STG;
#pragma unroll
        for (int it = 0; it < 8; ++it) {
            int idx = tid + it * 256;      // 2048: 1024 K + 1024 V
            int half = idx >> 10;
            int loc = idx & 1023;
            int r = loc >> 4, c = loc & 15;
            uint32_t so = r * 256 + (((uint32_t)(c ^ ((r & 1) << 2))) << 4);
            if (half == 0)
                cp16(st + so, k_ + (bh + n0k + r) * HD_ + c * 4);
            else
                cp16(st + A_VOFF + so, vT_ + (bh64 + r) * S_ + n0k + c * 4);
        }
        CP_COMMIT();
    };

    issue_kv(0, 0);

    float oacc[8][4];
    float mx[2] = {-1e30f, -1e30f};
    float li[2] = {0.f, 0.f};
#pragma unroll
    for (int dj = 0; dj < 8; ++dj)
#pragma unroll
        for (int q = 0; q < 4; ++q) oacc[dj][q] = 0.f;

    const int src0 = (lane & ~3) | (t >> 1);
    const int src1 = src0 + 2;

    const int nkv = S_ / 64;
    for (int kc = 0; kc < nkv; ++kc) {
        if (kc + 1 < nkv) { issue_kv((kc + 1) * 64, (kc + 1) & 1); CP_WAIT(1); }
        else              { CP_WAIT(0); }
        __syncthreads();
        char* st = sm + (kc & 1) * A_STG;

        // ---- S = Q K^T (16 x 64 per warp) ----
        float s[8][4];
#pragma unroll
        for (int nj = 0; nj < 8; ++nj)
#pragma unroll
            for (int q = 0; q < 4; ++q) s[nj][q] = 0.f;

#pragma unroll
        for (int ks2 = 0; ks2 < 4; ++ks2) {
#pragma unroll
            for (int nj = 0; nj < 8; ++nj) {
                int r = nj * 8 + g;
                int c = (ks2 * 4 + t) ^ ((r & 1) << 2);
                float4 v = *(float4*)(st + r * 256 + c * 16);
                mma_tf32(s[nj], qf[ks2*2],   __float_as_uint(v.x),
                         __float_as_uint(v.y));
                mma_tf32(s[nj], qf[ks2*2+1], __float_as_uint(v.z),
                         __float_as_uint(v.w));
            }
        }

        // ---- online softmax ----
#pragma unroll
        for (int ri = 0; ri < 2; ++ri) {
            float rm = -1e30f;
#pragma unroll
            for (int nj = 0; nj < 8; ++nj)
                rm = fmaxf(rm, fmaxf(s[nj][ri*2], s[nj][ri*2+1]));
            rm = fmaxf(rm, __shfl_xor_sync(0xffffffffu, rm, 1));
            rm = fmaxf(rm, __shfl_xor_sync(0xffffffffu, rm, 2));
            float mn   = fmaxf(mx[ri], rm);
            float corr = __expf(mx[ri] - mn);
            mx[ri] = mn;
            float rs = 0.f;
#pragma unroll
            for (int nj = 0; nj < 8; ++nj) {
                float p0 = __expf(s[nj][ri*2]   - mn);
                float p1 = __expf(s[nj][ri*2+1] - mn);
                s[nj][ri*2] = p0; s[nj][ri*2+1] = p1;
                rs += p0 + p1;
            }
            rs += __shfl_xor_sync(0xffffffffu, rs, 1);
            rs += __shfl_xor_sync(0xffffffffu, rs, 2);
            li[ri] = li[ri] * corr + rs;
#pragma unroll
            for (int dj = 0; dj < 8; ++dj) {
                oacc[dj][ri*2]   *= corr;
                oacc[dj][ri*2+1] *= corr;
            }
        }

        // ---- O += P V : build P A-frags via shfl, LDS.128 V covers 2 kk ----
#pragma unroll
        for (int kk2 = 0; kk2 < 4; ++kk2) {
            uint32_t pa[2][4];
#pragma unroll
            for (int e = 0; e < 2; ++e) {
                int kk = kk2 * 2 + e;
                float y00 = __shfl_sync(0xffffffffu, s[kk][0], src0);
                float y01 = __shfl_sync(0xffffffffu, s[kk][1], src0);
                float y10 = __shfl_sync(0xffffffffu, s[kk][0], src1);
                float y11 = __shfl_sync(0xffffffffu, s[kk][1], src1);
                float y20 = __shfl_sync(0xffffffffu, s[kk][2], src0);
                float y21 = __shfl_sync(0xffffffffu, s[kk][3], src0);
                float y30 = __shfl_sync(0xffffffffu, s[kk][2], src1);
                float y31 = __shfl_sync(0xffffffffu, s[kk][3], src1);
                pa[e][0] = __float_as_uint(rna_tf32((t & 1) ? y01 : y00));
                pa[e][1] = __float_as_uint(rna_tf32((t & 1) ? y21 : y20));
                pa[e][2] = __float_as_uint(rna_tf32((t & 1) ? y11 : y10));
                pa[e][3] = __float_as_uint(rna_tf32((t & 1) ? y31 : y30));
            }
#pragma unroll
            for (int dj = 0; dj < 8; ++dj) {
                int r = dj * 8 + g;
                int c = (kk2 * 4 + t) ^ ((r & 1) << 2);
                float4 v = *(float4*)(st + A_VOFF + r * 256 + c * 16);
                mma_tf32(oacc[dj], pa[0], __float_as_uint(v.x),
                         __float_as_uint(v.y));
                mma_tf32(oacc[dj], pa[1], __float_as_uint(v.z),
                         __float_as_uint(v.w));
            }
        }
        __syncthreads();
    }

    // ---- epilogue: normalize, round, write [B*S, perm16(D)] ----
#pragma unroll
    for (int ri = 0; ri < 2; ++ri) {
        float inv = 1.0f / li[ri];
        int srow = q0 + w * 16 + g + ri * 8;
        size_t rowo = ((size_t)(b * S_) + srow) * D_ + h * HD_;
#pragma unroll
        for (int dj = 0; dj < 8; ++dj) {
            int c = dj * 8 + 2 * t;
            o_[rowo + permk16(c)]     = rna_tf32(oacc[dj][ri*2]   * inv);
            o_[rowo + permk16(c + 1)] = rna_tf32(oacc[dj][ri*2+1] * inv);
        }
    }
}

// ---------------------------------------------------------------------------
extern "C" void kernel_launch(void* const* d_in, const int* in_sizes, int n_in,
                              void* d_out, int out_size)
{
    (void)in_sizes; (void)n_in; (void)out_size;
    const float* x     = (const float*)d_in[0];
    const float* w_qkv = (const float*)d_in[1];
    const float* w_out = (const float*)d_in[2];
    const float* b_out = (const float*)d_in[3];
    float* out = (float*)d_out;

    float *p_qkv, *p_x, *p_wq, *p_wo, *p_q, *p_k, *p_vT, *p_o;
    cudaGetSymbolAddress((void**)&p_qkv, g_qkv);
    cudaGetSymbolAddress((void**)&p_x,   g_x32);
    cudaGetSymbolAddress((void**)&p_wq,  g_wq32);
    cudaGetSymbolAddress((void**)&p_wo,  g_wo32);
    cudaGetSymbolAddress((void**)&p_q,   g_q32);
    cudaGetSymbolAddress((void**)&p_k,   g_k32);
    cudaGetSymbolAddress((void**)&p_vT,  g_vT32);
    cudaGetSymbolAddress((void**)&p_o,   g_o32);

    cudaFuncSetAttribute(gemm_tf32,
        cudaFuncAttributeMaxDynamicSharedMemorySize, GEMM_SMEM);
    cudaFuncSetAttribute(attn_tf32,
        cudaFuncAttributeMaxDynamicSharedMemorySize, ATT_SMEM);

    // 0) round+permute inputs / weights
    {
        int n4;
        n4 = (M_ * D_) / 4;
        cvt_perm4<<<(n4 + 255) / 256, 256>>>(x, p_x, n4, D_);
        n4 = (NQKV * D_) / 4;
        cvt_perm4<<<(n4 + 255) / 256, 256>>>(w_qkv, p_wq, n4, D_);
        n4 = (D_ * D_) / 4;
        cvt_perm4<<<(n4 + 255) / 256, 256>>>(w_out, p_wo, n4, D_);
    }
    // 1) QKV projection
    {
        dim3 grid(NQKV / 128, M_ / 128);
        gemm_tf32<<<grid, 256, GEMM_SMEM>>>(p_x, p_wq, nullptr, p_qkv,
                                            M_, NQKV, D_);
    }
    // 2) RoPE -> tf32 q/k/vT
    {
        int total = B_ * S_ * H_ * 32;
        rope_tf32<<<(total + 255) / 256, 256>>>(p_qkv, p_q, p_k, p_vT);
    }
    // 3) flash attention
    {
        dim3 grid(S_ / 128, H_, B_);
        attn_tf32<<<grid, 256, ATT_SMEM>>>(p_q, p_k, p_vT, p_o);
    }
    // 4) output projection + bias
    {
        dim3 grid(D_ / 128, M_ / 128);
        gemm_tf32<<<grid, 256, GEMM_SMEM>>>(p_o, p_wo, b_out, out,
                                            M_, D_, D_);
    }
}

// round 8
// speedup vs baseline: 3.7269x; 1.0480x over previous
#include <cuda_runtime.h>
#include <cuda_bf16.h>
#include <math.h>
#include <cstdint>

#define B_   2
#define S_   2048
#define D_   1024
#define H_   16
#define HD_  64
#define M_   (B_ * S_)      // 4096
#define NQKV (3 * D_)       // 3072

// ---------------- scratch (static device globals; no allocation) ----------
__device__ float g_qkv[(size_t)M_ * NQKV];      // fp32 [B*S, 3D] (natural)
__device__ float g_x32[(size_t)M_ * D_];        // tf32-rounded, k16-permuted
__device__ float g_wq32[(size_t)NQKV * D_];
__device__ float g_wo32[(size_t)D_ * D_];
__device__ float g_q32[(size_t)M_ * D_];        // [B,H,S,perm16(d)]
__device__ float g_k32[(size_t)M_ * D_];        // [B,H,S,perm16(d)]
__device__ float g_vT32[(size_t)M_ * D_];       // [B,H,d,perm16_s(S)]
__device__ float g_o32[(size_t)M_ * D_];        // [B*S, perm16(D)]

// =====================  helpers  ===========================================
__device__ __forceinline__ uint32_t smem_u32(const void* p) {
    uint32_t a;
    asm("{ .reg .u64 t; cvta.to.shared.u64 t, %1; cvt.u32.u64 %0, t; }"
        : "=r"(a) : "l"(p));
    return a;
}
__device__ __forceinline__ float rna_tf32(float x) {
    uint32_t u;
    asm("cvt.rna.tf32.f32 %0, %1;" : "=r"(u) : "f"(x));
    return __uint_as_float(u);
}
__device__ __forceinline__ void mma_tf32(float (&d)[4], const uint32_t (&a)[4],
                                         uint32_t b0, uint32_t b1) {
    asm volatile(
        "mma.sync.aligned.m16n8k8.row.col.f32.tf32.tf32.f32 "
        "{%0,%1,%2,%3}, {%4,%5,%6,%7}, {%8,%9}, {%0,%1,%2,%3};"
        : "+f"(d[0]), "+f"(d[1]), "+f"(d[2]), "+f"(d[3])
        : "r"(a[0]), "r"(a[1]), "r"(a[2]), "r"(a[3]), "r"(b0), "r"(b1));
}
__device__ __forceinline__ void cp16(uint32_t saddr, const void* gaddr) {
    asm volatile("cp.async.cg.shared.global [%0], [%1], 16;"
        :: "r"(saddr), "l"(gaddr));
}
#define CP_COMMIT() asm volatile("cp.async.commit_group;" ::: "memory")
#define CP_WAIT(n)  asm volatile("cp.async.wait_group %0;" :: "n"(n) : "memory")

// 16-wide k permutation: thread t's 4 values for 2 k-steps become one float4
__host__ __device__ __forceinline__ int p16(int u) {
    return ((u & 3) << 2) | ((u >> 2) & 3);
}
__host__ __device__ __forceinline__ int permk16(int k) {
    return (k & ~15) | p16(k & 15);
}

// ---------------------------------------------------------------------------
// cvt + permute (vectorized x4): dst[r][permk16(c)] = rna_tf32(src[r][c])
// ---------------------------------------------------------------------------
__global__ void cvt_perm4(const float* __restrict__ src, float* __restrict__ dst,
                          int n4, int cols)
{
    int i = blockIdx.x * blockDim.x + threadIdx.x;
    if (i >= n4) return;
    int cols4 = cols >> 2;
    int r  = i / cols4;
    int cq = i - r * cols4;
    float4 v = ((const float4*)src)[i];
    int q      = cq & 3;
    int base16 = (cq >> 2) << 4;
    float* drow = dst + (size_t)r * cols + base16 + q;
    drow[0]  = rna_tf32(v.x);
    drow[4]  = rna_tf32(v.y);
    drow[8]  = rna_tf32(v.z);
    drow[12] = rna_tf32(v.w);
}

// ---------------------------------------------------------------------------
// GEMM (NT) tf32: C[m,n] = sum_k A[m,k]*B[n,k] (+bias)
// CTA 256x128, 8 warps, warp tile 64x64. K-chunk 32, 3-stage cp.async.
// Loop order per iter: wait -> sync -> issue(kc+2) -> compute  (1 barrier).
// ---------------------------------------------------------------------------
#define G_BOFF 32768               // B tile offset within stage (A = 256*128B)
#define G_STG  49152               // 48KB per stage
#define GEMM_SMEM (3 * G_STG)      // 147456

__global__ void __launch_bounds__(256, 1) gemm_tf32(
    const float* __restrict__ A, const float* __restrict__ Bw,
    const float* __restrict__ bias, float* __restrict__ C,
    int M, int N, int K)
{
    extern __shared__ char sm[];
    const uint32_t sb = smem_u32(sm);
    const int tid  = threadIdx.x;
    const int lane = tid & 31;
    const int w    = tid >> 5;
    const int g    = lane >> 2;
    const int t    = lane & 3;
    const int m0 = blockIdx.y * 256;
    const int n0 = blockIdx.x * 128;
    const int wm = (w & 3) * 64;       // 4 m-groups over 256
    const int wn = (w >> 2) * 64;      // 2 n-groups over 128

    float acc[4][8][4];
#pragma unroll
    for (int mi = 0; mi < 4; ++mi)
#pragma unroll
        for (int nj = 0; nj < 8; ++nj)
#pragma unroll
            for (int q = 0; q < 4; ++q) acc[mi][nj][q] = 0.f;

    const int nch = K >> 5;

    auto issue = [&](int kc, int stg) {
        uint32_t st = sb + stg * G_STG;
#pragma unroll
        for (int it = 0; it < 8; ++it) {           // A: 256 rows x 8 chunks
            int idx = tid + it * 256;
            int r = idx >> 3, c = idx & 7;
            uint32_t so = r * 128 + (((uint32_t)(c ^ ((r & 1) << 2))) << 4);
            cp16(st + so, A + (size_t)(m0 + r) * K + kc * 32 + c * 4);
        }
#pragma unroll
        for (int it = 0; it < 4; ++it) {           // B: 128 rows x 8 chunks
            int idx = tid + it * 256;
            int r = idx >> 3, c = idx & 7;
            uint32_t so = r * 128 + (((uint32_t)(c ^ ((r & 1) << 2))) << 4);
            cp16(st + G_BOFF + so, Bw + (size_t)(n0 + r) * K + kc * 32 + c * 4);
        }
        CP_COMMIT();
    };

    issue(0, 0);
    if (nch > 1) issue(1, 1);

    for (int kc = 0; kc < nch; ++kc) {
        if (kc + 1 < nch) { CP_WAIT(1); }   // group kc complete (mine)
        else             { CP_WAIT(0); }
        __syncthreads();                    // publish all copies; all warps
                                            // finished compute(kc-1)
        if (kc + 2 < nch) issue(kc + 2, (kc + 2) % 3);
        char* st = sm + (kc % 3) * G_STG;

#pragma unroll
        for (int ks2 = 0; ks2 < 2; ++ks2) {
            float4 bf[8];
#pragma unroll
            for (int nj = 0; nj < 8; ++nj) {
                int r = wn + nj * 8 + g;
                int c = (ks2 * 4 + t) ^ ((r & 1) << 2);
                bf[nj] = *(float4*)(st + G_BOFF + r * 128 + c * 16);
            }
#pragma unroll
            for (int mi = 0; mi < 4; ++mi) {
                int r0 = wm + mi * 16 + g;
                int c  = (ks2 * 4 + t) ^ ((r0 & 1) << 2);
                float4 lo = *(float4*)(st + r0 * 128 + c * 16);
                float4 hi = *(float4*)(st + (r0 + 8) * 128 + c * 16);
                uint32_t ae[4] = {__float_as_uint(lo.x), __float_as_uint(hi.x),
                                  __float_as_uint(lo.y), __float_as_uint(hi.y)};
                uint32_t ao[4] = {__float_as_uint(lo.z), __float_as_uint(hi.z),
                                  __float_as_uint(lo.w), __float_as_uint(hi.w)};
#pragma unroll
                for (int nj = 0; nj < 8; ++nj) {
                    mma_tf32(acc[mi][nj], ae, __float_as_uint(bf[nj].x),
                             __float_as_uint(bf[nj].y));
                    mma_tf32(acc[mi][nj], ao, __float_as_uint(bf[nj].z),
                             __float_as_uint(bf[nj].w));
                }
            }
        }
    }

    const int c0 = t * 2;
#pragma unroll
    for (int mi = 0; mi < 4; ++mi) {
#pragma unroll
        for (int nj = 0; nj < 8; ++nj) {
            int m = m0 + wm + mi * 16 + g;
            int n = n0 + wn + nj * 8 + c0;
            float b0 = bias ? bias[n] : 0.f;
            float b1 = bias ? bias[n + 1] : 0.f;
            float2 v0 = {acc[mi][nj][0] + b0, acc[mi][nj][1] + b1};
            float2 v1 = {acc[mi][nj][2] + b0, acc[mi][nj][3] + b1};
            *(float2*)(C + (size_t)m * N + n)       = v0;
            *(float2*)(C + (size_t)(m + 8) * N + n) = v1;
        }
    }
}

// ---------------------------------------------------------------------------
// RoPE: fp32 qkv -> tf32 q/k [B,H,S,perm16(d)], v^T [B,H,d,perm16(s)].
// ---------------------------------------------------------------------------
__global__ void rope_tf32(const float* __restrict__ qkv,
                          float* __restrict__ q32, float* __restrict__ k32,
                          float* __restrict__ vT)
{
    int idx = blockIdx.x * blockDim.x + threadIdx.x;
    if (idx >= B_ * S_ * H_ * 32) return;
    int j = idx & 31;
    int h = (idx >> 5) & (H_ - 1);
    int s = (idx >> 9) & (S_ - 1);
    int b = idx >> 20;

    float tt  = (float)(2 * j) * (1.0f / (float)HD_);
    float inv = powf(10000.0f, -tt);
    float ang = (float)s * inv;
    float cs, sn;
    sincosf(ang, &sn, &cs);

    const float* row = qkv + ((size_t)(b * S_ + s)) * NQKV + h * HD_;
    float q1 = row[2 * j],          q2 = row[2 * j + 1];
    float k1 = row[D_ + 2 * j],     k2 = row[D_ + 2 * j + 1];
    float v1 = row[2 * D_ + 2 * j], v2 = row[2 * D_ + 2 * j + 1];

    size_t o = (((size_t)(b * H_ + h)) * S_ + s) * HD_;
    const float qs = 0.125f;
    q32[o + permk16(j)]      = rna_tf32((q1 * cs - q2 * sn) * qs);
    q32[o + permk16(j + 32)] = rna_tf32((q1 * sn + q2 * cs) * qs);
    k32[o + permk16(j)]      = rna_tf32(k1 * cs - k2 * sn);
    k32[o + permk16(j + 32)] = rna_tf32(k1 * sn + k2 * cs);

    int sp = (s & ~15) | p16(s & 15);
    size_t bh64 = ((size_t)(b * H_ + h)) * HD_;
    vT[(bh64 + 2 * j)     * S_ + sp] = rna_tf32(v1);
    vT[(bh64 + 2 * j + 1) * S_ + sp] = rna_tf32(v2);
}

// ---------------------------------------------------------------------------
// Flash attention, tf32 mma. 128 threads (4 warps), 32 q-rows/warp
// (q-tile 128), kv-tile 32, 3-stage cp.async.
// Loop order per iter: wait -> sync -> issue(kc+2) -> compute  (1 barrier).
// ---------------------------------------------------------------------------
#define A_VOFF 8192
#define A_STG  16384
#define ATT_SMEM (3 * A_STG)       // 49152

__global__ void __launch_bounds__(128, 2) attn_tf32(
    const float* __restrict__ q_, const float* __restrict__ k_,
    const float* __restrict__ vT_, float* __restrict__ o_)
{
    extern __shared__ char sm[];
    const uint32_t sb = smem_u32(sm);
    const int tid  = threadIdx.x;
    const int lane = tid & 31;
    const int w    = tid >> 5;
    const int g    = lane >> 2;
    const int t    = lane & 3;
    const int q0 = blockIdx.x * 128;
    const int h  = blockIdx.y;
    const int b  = blockIdx.z;
    const size_t bh   = ((size_t)(b * H_ + h)) * S_;
    const size_t bh64 = ((size_t)(b * H_ + h)) * HD_;

    // --- stage Q (128 rows x 256B = 32KB) into stages 0-1, extract frags ---
#pragma unroll
    for (int it = 0; it < 16; ++it) {
        int idx = tid + it * 128;          // 2048: 128 rows x 16 chunks
        int r = idx >> 4, c = idx & 15;
        uint32_t so = r * 256 + (((uint32_t)(c ^ ((r & 1) << 2))) << 4);
        cp16(sb + so, q_ + (bh + q0 + r) * HD_ + c * 4);
    }
    CP_COMMIT();
    CP_WAIT(0);
    __syncthreads();

    uint32_t qf[2][8][4];
#pragma unroll
    for (int rs = 0; rs < 2; ++rs) {
        int r0 = w * 32 + rs * 16 + g;
#pragma unroll
        for (int ks2 = 0; ks2 < 4; ++ks2) {
            int c = (ks2 * 4 + t) ^ ((r0 & 1) << 2);
            float4 lo = *(float4*)(sm + r0 * 256 + c * 16);
            float4 hi = *(float4*)(sm + (r0 + 8) * 256 + c * 16);
            qf[rs][ks2*2][0]   = __float_as_uint(lo.x);
            qf[rs][ks2*2][1]   = __float_as_uint(hi.x);
            qf[rs][ks2*2][2]   = __float_as_uint(lo.y);
            qf[rs][ks2*2][3]   = __float_as_uint(hi.y);
            qf[rs][ks2*2+1][0] = __float_as_uint(lo.z);
            qf[rs][ks2*2+1][1] = __float_as_uint(hi.z);
            qf[rs][ks2*2+1][2] = __float_as_uint(lo.w);
            qf[rs][ks2*2+1][3] = __float_as_uint(hi.w);
        }
    }
    __syncthreads();   // everyone done reading Q region

    auto issue_kv = [&](int n0k, int stg) {
        uint32_t st = sb + stg * A_STG;
#pragma unroll
        for (int it = 0; it < 4; ++it) {   // K: 32 rows x 16 chunks = 512
            int idx = tid + it * 128;
            int r = idx >> 4, c = idx & 15;
            uint32_t so = r * 256 + (((uint32_t)(c ^ ((r & 1) << 2))) << 4);
            cp16(st + so, k_ + (bh + n0k + r) * HD_ + c * 4);
        }
#pragma unroll
        for (int it = 0; it < 4; ++it) {   // V: 64 rows x 8 chunks = 512
            int idx = tid + it * 128;
            int r = idx >> 3, c = idx & 7;
            uint32_t so = r * 128 + (((uint32_t)(c ^ ((r & 1) << 2))) << 4);
            cp16(st + A_VOFF + so, vT_ + (bh64 + r) * S_ + n0k + c * 4);
        }
        CP_COMMIT();
    };

    issue_kv(0, 0);
    issue_kv(32, 1);

    float oacc[2][8][4];
    float mx[2][2] = {{-1e30f, -1e30f}, {-1e30f, -1e30f}};
    float li[2][2] = {{0.f, 0.f}, {0.f, 0.f}};
#pragma unroll
    for (int rs = 0; rs < 2; ++rs)
#pragma unroll
        for (int dj = 0; dj < 8; ++dj)
#pragma unroll
            for (int q = 0; q < 4; ++q) oacc[rs][dj][q] = 0.f;

    const int src0 = (lane & ~3) | (t >> 1);
    const int src1 = src0 + 2;

    const int nkv = S_ / 32;
    for (int kc = 0; kc < nkv; ++kc) {
        if (kc + 1 < nkv) { CP_WAIT(1); }
        else              { CP_WAIT(0); }
        __syncthreads();
        if (kc + 2 < nkv) issue_kv((kc + 2) * 32, (kc + 2) % 3);
        char* st = sm + (kc % 3) * A_STG;

        // ---- S = Q K^T : per warp 32q x 32kv ----
        float s[2][4][4];
#pragma unroll
        for (int rs = 0; rs < 2; ++rs)
#pragma unroll
            for (int nj = 0; nj < 4; ++nj)
#pragma unroll
                for (int q = 0; q < 4; ++q) s[rs][nj][q] = 0.f;

#pragma unroll
        for (int ks2 = 0; ks2 < 4; ++ks2) {
#pragma unroll
            for (int nj = 0; nj < 4; ++nj) {
                int r = nj * 8 + g;
                int c = (ks2 * 4 + t) ^ ((r & 1) << 2);
                float4 v = *(float4*)(st + r * 256 + c * 16);
                uint32_t vx = __float_as_uint(v.x), vy = __float_as_uint(v.y);
                uint32_t vz = __float_as_uint(v.z), vw = __float_as_uint(v.w);
#pragma unroll
                for (int rs = 0; rs < 2; ++rs) {
                    mma_tf32(s[rs][nj], qf[rs][ks2*2],   vx, vy);
                    mma_tf32(s[rs][nj], qf[rs][ks2*2+1], vz, vw);
                }
            }
        }

        // ---- online softmax ----
#pragma unroll
        for (int rs = 0; rs < 2; ++rs) {
#pragma unroll
            for (int ri = 0; ri < 2; ++ri) {
                float rm = -1e30f;
#pragma unroll
                for (int nj = 0; nj < 4; ++nj)
                    rm = fmaxf(rm, fmaxf(s[rs][nj][ri*2], s[rs][nj][ri*2+1]));
                rm = fmaxf(rm, __shfl_xor_sync(0xffffffffu, rm, 1));
                rm = fmaxf(rm, __shfl_xor_sync(0xffffffffu, rm, 2));
                float mn   = fmaxf(mx[rs][ri], rm);
                float corr = __expf(mx[rs][ri] - mn);
                mx[rs][ri] = mn;
                float rsum = 0.f;
#pragma unroll
                for (int nj = 0; nj < 4; ++nj) {
                    float p0 = __expf(s[rs][nj][ri*2]   - mn);
                    float p1 = __expf(s[rs][nj][ri*2+1] - mn);
                    s[rs][nj][ri*2] = p0; s[rs][nj][ri*2+1] = p1;
                    rsum += p0 + p1;
                }
                rsum += __shfl_xor_sync(0xffffffffu, rsum, 1);
                rsum += __shfl_xor_sync(0xffffffffu, rsum, 2);
                li[rs][ri] = li[rs][ri] * corr + rsum;
#pragma unroll
                for (int dj = 0; dj < 8; ++dj) {
                    oacc[rs][dj][ri*2]   *= corr;
                    oacc[rs][dj][ri*2+1] *= corr;
                }
            }
        }

        // ---- O += P V ----
#pragma unroll
        for (int kk2 = 0; kk2 < 2; ++kk2) {
            uint32_t pa[2][2][4];
#pragma unroll
            for (int rs = 0; rs < 2; ++rs)
#pragma unroll
                for (int e = 0; e < 2; ++e) {
                    int kk = kk2 * 2 + e;
                    float y00 = __shfl_sync(0xffffffffu, s[rs][kk][0], src0);
                    float y01 = __shfl_sync(0xffffffffu, s[rs][kk][1], src0);
                    float y10 = __shfl_sync(0xffffffffu, s[rs][kk][0], src1);
                    float y11 = __shfl_sync(0xffffffffu, s[rs][kk][1], src1);
                    float y20 = __shfl_sync(0xffffffffu, s[rs][kk][2], src0);
                    float y21 = __shfl_sync(0xffffffffu, s[rs][kk][3], src0);
                    float y30 = __shfl_sync(0xffffffffu, s[rs][kk][2], src1);
                    float y31 = __shfl_sync(0xffffffffu, s[rs][kk][3], src1);
                    pa[rs][e][0] = __float_as_uint(rna_tf32((t & 1) ? y01 : y00));
                    pa[rs][e][1] = __float_as_uint(rna_tf32((t & 1) ? y21 : y20));
                    pa[rs][e][2] = __float_as_uint(rna_tf32((t & 1) ? y11 : y10));
                    pa[rs][e][3] = __float_as_uint(rna_tf32((t & 1) ? y31 : y30));
                }
#pragma unroll
            for (int dj = 0; dj < 8; ++dj) {
                int r = dj * 8 + g;
                int c = (kk2 * 4 + t) ^ ((r & 1) << 2);
                float4 v = *(float4*)(st + A_VOFF + r * 128 + c * 16);
                uint32_t vx = __float_as_uint(v.x), vy = __float_as_uint(v.y);
                uint32_t vz = __float_as_uint(v.z), vw = __float_as_uint(v.w);
#pragma unroll
                for (int rs = 0; rs < 2; ++rs) {
                    mma_tf32(oacc[rs][dj], pa[rs][0], vx, vy);
                    mma_tf32(oacc[rs][dj], pa[rs][1], vz, vw);
                }
            }
        }
    }

    // ---- epilogue: normalize, round, write [B*S, perm16(D)] ----
#pragma unroll
    for (int rs = 0; rs < 2; ++rs) {
#pragma unroll
        for (int ri = 0; ri < 2; ++ri) {
            float inv = 1.0f / li[rs][ri];
            int srow = q0 + w * 32 + rs * 16 + g + ri * 8;
            size_t rowo = ((size_t)(b * S_) + srow) * D_ + h * HD_;
#pragma unroll
            for (int dj = 0; dj < 8; ++dj) {
                int c = dj * 8 + 2 * t;
                o_[rowo + permk16(c)]     = rna_tf32(oacc[rs][dj][ri*2]   * inv);
                o_[rowo + permk16(c + 1)] = rna_tf32(oacc[rs][dj][ri*2+1] * inv);
            }
        }
    }
}

// ---------------------------------------------------------------------------
extern "C" void kernel_launch(void* const* d_in, const int* in_sizes, int n_in,
                              void* d_out, int out_size)
{
    (void)in_sizes; (void)n_in; (void)out_size;
    const float* x     = (const float*)d_in[0];
    const float* w_qkv = (const float*)d_in[1];
    const float* w_out = (const float*)d_in[2];
    const float* b_out = (const float*)d_in[3];
    float* out = (float*)d_out;

    float *p_qkv, *p_x, *p_wq, *p_wo, *p_q, *p_k, *p_vT, *p_o;
    cudaGetSymbolAddress((void**)&p_qkv, g_qkv);
    cudaGetSymbolAddress((void**)&p_x,   g_x32);
    cudaGetSymbolAddress((void**)&p_wq,  g_wq32);
    cudaGetSymbolAddress((void**)&p_wo,  g_wo32);
    cudaGetSymbolAddress((void**)&p_q,   g_q32);
    cudaGetSymbolAddress((void**)&p_k,   g_k32);
    cudaGetSymbolAddress((void**)&p_vT,  g_vT32);
    cudaGetSymbolAddress((void**)&p_o,   g_o32);

    cudaFuncSetAttribute(gemm_tf32,
        cudaFuncAttributeMaxDynamicSharedMemorySize, GEMM_SMEM);
    cudaFuncSetAttribute(attn_tf32,
        cudaFuncAttributeMaxDynamicSharedMemorySize, ATT_SMEM);

    // 0) round+permute inputs / weights
    {
        int n4;
        n4 = (M_ * D_) / 4;
        cvt_perm4<<<(n4 + 255) / 256, 256>>>(x, p_x, n4, D_);
        n4 = (NQKV * D_) / 4;
        cvt_perm4<<<(n4 + 255) / 256, 256>>>(w_qkv, p_wq, n4, D_);
        n4 = (D_ * D_) / 4;
        cvt_perm4<<<(n4 + 255) / 256, 256>>>(w_out, p_wo, n4, D_);
    }
    // 1) QKV projection: [4096 x 1024] x [3072 x 1024]^T
    {
        dim3 grid(NQKV / 128, M_ / 256);
        gemm_tf32<<<grid, 256, GEMM_SMEM>>>(p_x, p_wq, nullptr, p_qkv,
                                            M_, NQKV, D_);
    }
    // 2) RoPE -> tf32 q/k/vT
    {
        int total = B_ * S_ * H_ * 32;
        rope_tf32<<<(total + 255) / 256, 256>>>(p_qkv, p_q, p_k, p_vT);
    }
    // 3) flash attention
    {
        dim3 grid(S_ / 128, H_, B_);
        attn_tf32<<<grid, 128, ATT_SMEM>>>(p_q, p_k, p_vT, p_o);
    }
    // 4) output projection + bias
    {
        dim3 grid(D_ / 128, M_ / 256);
        gemm_tf32<<<grid, 256, GEMM_SMEM>>>(p_o, p_wo, b_out, out,
                                            M_, D_, D_);
    }
}

// round 9
// speedup vs baseline: 3.7604x; 1.0090x over previous
#include <cuda_runtime.h>
#include <cuda_bf16.h>
#include <math.h>
#include <cstdint>

#define B_   2
#define S_   2048
#define D_   1024
#define H_   16
#define HD_  64
#define M_   (B_ * S_)      // 4096
#define NQKV (3 * D_)       // 3072

// ---------------- scratch (static device globals; no allocation) ----------
__device__ float g_qkv[(size_t)M_ * NQKV];      // fp32 [B*S, 3D] (natural)
__device__ float g_x32[(size_t)M_ * D_];        // tf32-rounded, k16-permuted
__device__ float g_wq32[(size_t)NQKV * D_];
__device__ float g_wo32[(size_t)D_ * D_];
__device__ float g_q32[(size_t)M_ * D_];        // [B,H,S,perm16(d)]
__device__ float g_k32[(size_t)M_ * D_];        // [B,H,S,perm16(d)]
__device__ float g_vT32[(size_t)M_ * D_];       // [B,H,d,perm16_s(S)]
__device__ float g_o32[(size_t)M_ * D_];        // [B*S, perm16(D)]

// =====================  helpers  ===========================================
__device__ __forceinline__ uint32_t smem_u32(const void* p) {
    uint32_t a;
    asm("{ .reg .u64 t; cvta.to.shared.u64 t, %1; cvt.u32.u64 %0, t; }"
        : "=r"(a) : "l"(p));
    return a;
}
__device__ __forceinline__ float rna_tf32(float x) {
    uint32_t u;
    asm("cvt.rna.tf32.f32 %0, %1;" : "=r"(u) : "f"(x));
    return __uint_as_float(u);
}
__device__ __forceinline__ void mma_tf32(float (&d)[4], const uint32_t (&a)[4],
                                         uint32_t b0, uint32_t b1) {
    asm volatile(
        "mma.sync.aligned.m16n8k8.row.col.f32.tf32.tf32.f32 "
        "{%0,%1,%2,%3}, {%4,%5,%6,%7}, {%8,%9}, {%0,%1,%2,%3};"
        : "+f"(d[0]), "+f"(d[1]), "+f"(d[2]), "+f"(d[3])
        : "r"(a[0]), "r"(a[1]), "r"(a[2]), "r"(a[3]), "r"(b0), "r"(b1));
}
__device__ __forceinline__ void cp16(uint32_t saddr, const void* gaddr) {
    asm volatile("cp.async.cg.shared.global [%0], [%1], 16;"
        :: "r"(saddr), "l"(gaddr));
}
#define CP_COMMIT() asm volatile("cp.async.commit_group;" ::: "memory")
#define CP_WAIT(n)  asm volatile("cp.async.wait_group %0;" :: "n"(n) : "memory")

// 16-wide k permutation: thread t's 4 values for 2 k-steps become one float4
__host__ __device__ __forceinline__ int p16(int u) {
    return ((u & 3) << 2) | ((u >> 2) & 3);
}
__host__ __device__ __forceinline__ int permk16(int k) {
    return (k & ~15) | p16(k & 15);
}

// ---------------------------------------------------------------------------
// cvt + permute (vectorized x4): dst[r][permk16(c)] = rna_tf32(src[r][c])
// ---------------------------------------------------------------------------
__global__ void cvt_perm4(const float* __restrict__ src, float* __restrict__ dst,
                          int n4, int cols)
{
    int i = blockIdx.x * blockDim.x + threadIdx.x;
    if (i >= n4) return;
    int cols4 = cols >> 2;
    int r  = i / cols4;
    int cq = i - r * cols4;
    float4 v = ((const float4*)src)[i];
    int q      = cq & 3;
    int base16 = (cq >> 2) << 4;
    float* drow = dst + (size_t)r * cols + base16 + q;
    drow[0]  = rna_tf32(v.x);
    drow[4]  = rna_tf32(v.y);
    drow[8]  = rna_tf32(v.z);
    drow[12] = rna_tf32(v.w);
}

// ---------------------------------------------------------------------------
// GEMM (NT) tf32: C[m,n] = sum_k A[m,k]*B[n,k] (+bias)
// CTA 256x128, 8 warps, warp tile 64x64. K-chunk 32, 3-stage cp.async.
// Even/odd k-step MMAs split into separate passes (no accumulator RAW
// back-to-back). Per-accumulator op order unchanged (bit-identical).
// ---------------------------------------------------------------------------
#define G_BOFF 32768               // B tile offset within stage (A = 256*128B)
#define G_STG  49152               // 48KB per stage
#define GEMM_SMEM (3 * G_STG)      // 147456

__global__ void __launch_bounds__(256, 1) gemm_tf32(
    const float* __restrict__ A, const float* __restrict__ Bw,
    const float* __restrict__ bias, float* __restrict__ C,
    int M, int N, int K)
{
    extern __shared__ char sm[];
    const uint32_t sb = smem_u32(sm);
    const int tid  = threadIdx.x;
    const int lane = tid & 31;
    const int w    = tid >> 5;
    const int g    = lane >> 2;
    const int t    = lane & 3;
    const int m0 = blockIdx.y * 256;
    const int n0 = blockIdx.x * 128;
    const int wm = (w & 3) * 64;       // 4 m-groups over 256
    const int wn = (w >> 2) * 64;      // 2 n-groups over 128

    float acc[4][8][4];
#pragma unroll
    for (int mi = 0; mi < 4; ++mi)
#pragma unroll
        for (int nj = 0; nj < 8; ++nj)
#pragma unroll
            for (int q = 0; q < 4; ++q) acc[mi][nj][q] = 0.f;

    const int nch = K >> 5;

    auto issue = [&](int kc, int stg) {
        uint32_t st = sb + stg * G_STG;
#pragma unroll
        for (int it = 0; it < 8; ++it) {           // A: 256 rows x 8 chunks
            int idx = tid + it * 256;
            int r = idx >> 3, c = idx & 7;
            uint32_t so = r * 128 + (((uint32_t)(c ^ ((r & 1) << 2))) << 4);
            cp16(st + so, A + (size_t)(m0 + r) * K + kc * 32 + c * 4);
        }
#pragma unroll
        for (int it = 0; it < 4; ++it) {           // B: 128 rows x 8 chunks
            int idx = tid + it * 256;
            int r = idx >> 3, c = idx & 7;
            uint32_t so = r * 128 + (((uint32_t)(c ^ ((r & 1) << 2))) << 4);
            cp16(st + G_BOFF + so, Bw + (size_t)(n0 + r) * K + kc * 32 + c * 4);
        }
        CP_COMMIT();
    };

    issue(0, 0);
    if (nch > 1) issue(1, 1);

    for (int kc = 0; kc < nch; ++kc) {
        if (kc + 1 < nch) { CP_WAIT(1); }
        else             { CP_WAIT(0); }
        __syncthreads();
        if (kc + 2 < nch) issue(kc + 2, (kc + 2) % 3);
        char* st = sm + (kc % 3) * G_STG;

#pragma unroll
        for (int ks2 = 0; ks2 < 2; ++ks2) {
            float4 bf[8];
#pragma unroll
            for (int nj = 0; nj < 8; ++nj) {
                int r = wn + nj * 8 + g;
                int c = (ks2 * 4 + t) ^ ((r & 1) << 2);
                bf[nj] = *(float4*)(st + G_BOFF + r * 128 + c * 16);
            }
#pragma unroll
            for (int mi = 0; mi < 4; ++mi) {
                int r0 = wm + mi * 16 + g;
                int c  = (ks2 * 4 + t) ^ ((r0 & 1) << 2);
                float4 lo = *(float4*)(st + r0 * 128 + c * 16);
                float4 hi = *(float4*)(st + (r0 + 8) * 128 + c * 16);
                uint32_t ae[4] = {__float_as_uint(lo.x), __float_as_uint(hi.x),
                                  __float_as_uint(lo.y), __float_as_uint(hi.y)};
                uint32_t ao[4] = {__float_as_uint(lo.z), __float_as_uint(hi.z),
                                  __float_as_uint(lo.w), __float_as_uint(hi.w)};
                // even k-step pass (8 independent accumulators)
#pragma unroll
                for (int nj = 0; nj < 8; ++nj)
                    mma_tf32(acc[mi][nj], ae, __float_as_uint(bf[nj].x),
                             __float_as_uint(bf[nj].y));
                // odd k-step pass
#pragma unroll
                for (int nj = 0; nj < 8; ++nj)
                    mma_tf32(acc[mi][nj], ao, __float_as_uint(bf[nj].z),
                             __float_as_uint(bf[nj].w));
            }
        }
    }

    const int c0 = t * 2;
#pragma unroll
    for (int mi = 0; mi < 4; ++mi) {
#pragma unroll
        for (int nj = 0; nj < 8; ++nj) {
            int m = m0 + wm + mi * 16 + g;
            int n = n0 + wn + nj * 8 + c0;
            float b0 = bias ? bias[n] : 0.f;
            float b1 = bias ? bias[n + 1] : 0.f;
            float2 v0 = {acc[mi][nj][0] + b0, acc[mi][nj][1] + b1};
            float2 v1 = {acc[mi][nj][2] + b0, acc[mi][nj][3] + b1};
            *(float2*)(C + (size_t)m * N + n)       = v0;
            *(float2*)(C + (size_t)(m + 8) * N + n) = v1;
        }
    }
}

// ---------------------------------------------------------------------------
// RoPE: fp32 qkv -> tf32 q/k [B,H,S,perm16(d)], v^T [B,H,d,perm16(s)].
// ---------------------------------------------------------------------------
__global__ void rope_tf32(const float* __restrict__ qkv,
                          float* __restrict__ q32, float* __restrict__ k32,
                          float* __restrict__ vT)
{
    int idx = blockIdx.x * blockDim.x + threadIdx.x;
    if (idx >= B_ * S_ * H_ * 32) return;
    int j = idx & 31;
    int h = (idx >> 5) & (H_ - 1);
    int s = (idx >> 9) & (S_ - 1);
    int b = idx >> 20;

    float tt  = (float)(2 * j) * (1.0f / (float)HD_);
    float inv = powf(10000.0f, -tt);
    float ang = (float)s * inv;
    float cs, sn;
    sincosf(ang, &sn, &cs);

    const float* row = qkv + ((size_t)(b * S_ + s)) * NQKV + h * HD_;
    float q1 = row[2 * j],          q2 = row[2 * j + 1];
    float k1 = row[D_ + 2 * j],     k2 = row[D_ + 2 * j + 1];
    float v1 = row[2 * D_ + 2 * j], v2 = row[2 * D_ + 2 * j + 1];

    size_t o = (((size_t)(b * H_ + h)) * S_ + s) * HD_;
    const float qs = 0.125f;
    q32[o + permk16(j)]      = rna_tf32((q1 * cs - q2 * sn) * qs);
    q32[o + permk16(j + 32)] = rna_tf32((q1 * sn + q2 * cs) * qs);
    k32[o + permk16(j)]      = rna_tf32(k1 * cs - k2 * sn);
    k32[o + permk16(j + 32)] = rna_tf32(k1 * sn + k2 * cs);

    int sp = (s & ~15) | p16(s & 15);
    size_t bh64 = ((size_t)(b * H_ + h)) * HD_;
    vT[(bh64 + 2 * j)     * S_ + sp] = rna_tf32(v1);
    vT[(bh64 + 2 * j + 1) * S_ + sp] = rna_tf32(v2);
}

// ---------------------------------------------------------------------------
// Flash attention, tf32 mma. 128 threads (4 warps), 32 q-rows/warp
// (q-tile 128), kv-tile 32, 3-stage cp.async, even/odd MMA passes split.
// ---------------------------------------------------------------------------
#define A_VOFF 8192
#define A_STG  16384
#define ATT_SMEM (3 * A_STG)       // 49152

__global__ void __launch_bounds__(128, 2) attn_tf32(
    const float* __restrict__ q_, const float* __restrict__ k_,
    const float* __restrict__ vT_, float* __restrict__ o_)
{
    extern __shared__ char sm[];
    const uint32_t sb = smem_u32(sm);
    const int tid  = threadIdx.x;
    const int lane = tid & 31;
    const int w    = tid >> 5;
    const int g    = lane >> 2;
    const int t    = lane & 3;
    const int q0 = blockIdx.x * 128;
    const int h  = blockIdx.y;
    const int b  = blockIdx.z;
    const size_t bh   = ((size_t)(b * H_ + h)) * S_;
    const size_t bh64 = ((size_t)(b * H_ + h)) * HD_;

    // --- stage Q (128 rows x 256B = 32KB) into stages 0-1, extract frags ---
#pragma unroll
    for (int it = 0; it < 16; ++it) {
        int idx = tid + it * 128;          // 2048: 128 rows x 16 chunks
        int r = idx >> 4, c = idx & 15;
        uint32_t so = r * 256 + (((uint32_t)(c ^ ((r & 1) << 2))) << 4);
        cp16(sb + so, q_ + (bh + q0 + r) * HD_ + c * 4);
    }
    CP_COMMIT();
    CP_WAIT(0);
    __syncthreads();

    uint32_t qf[2][8][4];
#pragma unroll
    for (int rs = 0; rs < 2; ++rs) {
        int r0 = w * 32 + rs * 16 + g;
#pragma unroll
        for (int ks2 = 0; ks2 < 4; ++ks2) {
            int c = (ks2 * 4 + t) ^ ((r0 & 1) << 2);
            float4 lo = *(float4*)(sm + r0 * 256 + c * 16);
            float4 hi = *(float4*)(sm + (r0 + 8) * 256 + c * 16);
            qf[rs][ks2*2][0]   = __float_as_uint(lo.x);
            qf[rs][ks2*2][1]   = __float_as_uint(hi.x);
            qf[rs][ks2*2][2]   = __float_as_uint(lo.y);
            qf[rs][ks2*2][3]   = __float_as_uint(hi.y);
            qf[rs][ks2*2+1][0] = __float_as_uint(lo.z);
            qf[rs][ks2*2+1][1] = __float_as_uint(hi.z);
            qf[rs][ks2*2+1][2] = __float_as_uint(lo.w);
            qf[rs][ks2*2+1][3] = __float_as_uint(hi.w);
        }
    }
    __syncthreads();   // everyone done reading Q region

    auto issue_kv = [&](int n0k, int stg) {
        uint32_t st = sb + stg * A_STG;
#pragma unroll
        for (int it = 0; it < 4; ++it) {   // K: 32 rows x 16 chunks = 512
            int idx = tid + it * 128;
            int r = idx >> 4, c = idx & 15;
            uint32_t so = r * 256 + (((uint32_t)(c ^ ((r & 1) << 2))) << 4);
            cp16(st + so, k_ + (bh + n0k + r) * HD_ + c * 4);
        }
#pragma unroll
        for (int it = 0; it < 4; ++it) {   // V: 64 rows x 8 chunks = 512
            int idx = tid + it * 128;
            int r = idx >> 3, c = idx & 7;
            uint32_t so = r * 128 + (((uint32_t)(c ^ ((r & 1) << 2))) << 4);
            cp16(st + A_VOFF + so, vT_ + (bh64 + r) * S_ + n0k + c * 4);
        }
        CP_COMMIT();
    };

    issue_kv(0, 0);
    issue_kv(32, 1);

    float oacc[2][8][4];
    float mx[2][2] = {{-1e30f, -1e30f}, {-1e30f, -1e30f}};
    float li[2][2] = {{0.f, 0.f}, {0.f, 0.f}};
#pragma unroll
    for (int rs = 0; rs < 2; ++rs)
#pragma unroll
        for (int dj = 0; dj < 8; ++dj)
#pragma unroll
            for (int q = 0; q < 4; ++q) oacc[rs][dj][q] = 0.f;

    const int src0 = (lane & ~3) | (t >> 1);
    const int src1 = src0 + 2;

    const int nkv = S_ / 32;
    for (int kc = 0; kc < nkv; ++kc) {
        if (kc + 1 < nkv) { CP_WAIT(1); }
        else              { CP_WAIT(0); }
        __syncthreads();
        if (kc + 2 < nkv) issue_kv((kc + 2) * 32, (kc + 2) % 3);
        char* st = sm + (kc % 3) * A_STG;

        // ---- S = Q K^T : per warp 32q x 32kv ----
        float s[2][4][4];
#pragma unroll
        for (int rs = 0; rs < 2; ++rs)
#pragma unroll
            for (int nj = 0; nj < 4; ++nj)
#pragma unroll
                for (int q = 0; q < 4; ++q) s[rs][nj][q] = 0.f;

#pragma unroll
        for (int ks2 = 0; ks2 < 4; ++ks2) {
            float4 kv4[4];
#pragma unroll
            for (int nj = 0; nj < 4; ++nj) {
                int r = nj * 8 + g;
                int c = (ks2 * 4 + t) ^ ((r & 1) << 2);
                kv4[nj] = *(float4*)(st + r * 256 + c * 16);
            }
            // even k-step pass (8 independent accumulators)
#pragma unroll
            for (int rs = 0; rs < 2; ++rs)
#pragma unroll
                for (int nj = 0; nj < 4; ++nj)
                    mma_tf32(s[rs][nj], qf[rs][ks2*2],
                             __float_as_uint(kv4[nj].x),
                             __float_as_uint(kv4[nj].y));
            // odd k-step pass
#pragma unroll
            for (int rs = 0; rs < 2; ++rs)
#pragma unroll
                for (int nj = 0; nj < 4; ++nj)
                    mma_tf32(s[rs][nj], qf[rs][ks2*2+1],
                             __float_as_uint(kv4[nj].z),
                             __float_as_uint(kv4[nj].w));
        }

        // ---- online softmax ----
#pragma unroll
        for (int rs = 0; rs < 2; ++rs) {
#pragma unroll
            for (int ri = 0; ri < 2; ++ri) {
                float rm = -1e30f;
#pragma unroll
                for (int nj = 0; nj < 4; ++nj)
                    rm = fmaxf(rm, fmaxf(s[rs][nj][ri*2], s[rs][nj][ri*2+1]));
                rm = fmaxf(rm, __shfl_xor_sync(0xffffffffu, rm, 1));
                rm = fmaxf(rm, __shfl_xor_sync(0xffffffffu, rm, 2));
                float mn   = fmaxf(mx[rs][ri], rm);
                float corr = __expf(mx[rs][ri] - mn);
                mx[rs][ri] = mn;
                float rsum = 0.f;
#pragma unroll
                for (int nj = 0; nj < 4; ++nj) {
                    float p0 = __expf(s[rs][nj][ri*2]   - mn);
                    float p1 = __expf(s[rs][nj][ri*2+1] - mn);
                    s[rs][nj][ri*2] = p0; s[rs][nj][ri*2+1] = p1;
                    rsum += p0 + p1;
                }
                rsum += __shfl_xor_sync(0xffffffffu, rsum, 1);
                rsum += __shfl_xor_sync(0xffffffffu, rsum, 2);
                li[rs][ri] = li[rs][ri] * corr + rsum;
#pragma unroll
                for (int dj = 0; dj < 8; ++dj) {
                    oacc[rs][dj][ri*2]   *= corr;
                    oacc[rs][dj][ri*2+1] *= corr;
                }
            }
        }

        // ---- O += P V : even/odd passes over dj-groups of 4 ----
#pragma unroll
        for (int kk2 = 0; kk2 < 2; ++kk2) {
            uint32_t pa[2][2][4];
#pragma unroll
            for (int rs = 0; rs < 2; ++rs)
#pragma unroll
                for (int e = 0; e < 2; ++e) {
                    int kk = kk2 * 2 + e;
                    float y00 = __shfl_sync(0xffffffffu, s[rs][kk][0], src0);
                    float y01 = __shfl_sync(0xffffffffu, s[rs][kk][1], src0);
                    float y10 = __shfl_sync(0xffffffffu, s[rs][kk][0], src1);
                    float y11 = __shfl_sync(0xffffffffu, s[rs][kk][1], src1);
                    float y20 = __shfl_sync(0xffffffffu, s[rs][kk][2], src0);
                    float y21 = __shfl_sync(0xffffffffu, s[rs][kk][3], src0);
                    float y30 = __shfl_sync(0xffffffffu, s[rs][kk][2], src1);
                    float y31 = __shfl_sync(0xffffffffu, s[rs][kk][3], src1);
                    pa[rs][e][0] = __float_as_uint(rna_tf32((t & 1) ? y01 : y00));
                    pa[rs][e][1] = __float_as_uint(rna_tf32((t & 1) ? y21 : y20));
                    pa[rs][e][2] = __float_as_uint(rna_tf32((t & 1) ? y11 : y10));
                    pa[rs][e][3] = __float_as_uint(rna_tf32((t & 1) ? y31 : y30));
                }
#pragma unroll
            for (int djg = 0; djg < 2; ++djg) {
                float4 vv[4];
#pragma unroll
                for (int u = 0; u < 4; ++u) {
                    int dj = djg * 4 + u;
                    int r = dj * 8 + g;
                    int c = (kk2 * 4 + t) ^ ((r & 1) << 2);
                    vv[u] = *(float4*)(st + A_VOFF + r * 128 + c * 16);
                }
                // even k pass
#pragma unroll
                for (int u = 0; u < 4; ++u)
#pragma unroll
                    for (int rs = 0; rs < 2; ++rs)
                        mma_tf32(oacc[rs][djg*4+u], pa[rs][0],
                                 __float_as_uint(vv[u].x),
                                 __float_as_uint(vv[u].y));
                // odd k pass
#pragma unroll
                for (int u = 0; u < 4; ++u)
#pragma unroll
                    for (int rs = 0; rs < 2; ++rs)
                        mma_tf32(oacc[rs][djg*4+u], pa[rs][1],
                                 __float_as_uint(vv[u].z),
                                 __float_as_uint(vv[u].w));
            }
        }
    }

    // ---- epilogue: normalize, round, write [B*S, perm16(D)] ----
#pragma unroll
    for (int rs = 0; rs < 2; ++rs) {
#pragma unroll
        for (int ri = 0; ri < 2; ++ri) {
            float inv = 1.0f / li[rs][ri];
            int srow = q0 + w * 32 + rs * 16 + g + ri * 8;
            size_t rowo = ((size_t)(b * S_) + srow) * D_ + h * HD_;
#pragma unroll
            for (int dj = 0; dj < 8; ++dj) {
                int c = dj * 8 + 2 * t;
                o_[rowo + permk16(c)]     = rna_tf32(oacc[rs][dj][ri*2]   * inv);
                o_[rowo + permk16(c + 1)] = rna_tf32(oacc[rs][dj][ri*2+1] * inv);
            }
        }
    }
}

// ---------------------------------------------------------------------------
extern "C" void kernel_launch(void* const* d_in, const int* in_sizes, int n_in,
                              void* d_out, int out_size)
{
    (void)in_sizes; (void)n_in; (void)out_size;
    const float* x     = (const float*)d_in[0];
    const float* w_qkv = (const float*)d_in[1];
    const float* w_out = (const float*)d_in[2];
    const float* b_out = (const float*)d_in[3];
    float* out = (float*)d_out;

    float *p_qkv, *p_x, *p_wq, *p_wo, *p_q, *p_k, *p_vT, *p_o;
    cudaGetSymbolAddress((void**)&p_qkv, g_qkv);
    cudaGetSymbolAddress((void**)&p_x,   g_x32);
    cudaGetSymbolAddress((void**)&p_wq,  g_wq32);
    cudaGetSymbolAddress((void**)&p_wo,  g_wo32);
    cudaGetSymbolAddress((void**)&p_q,   g_q32);
    cudaGetSymbolAddress((void**)&p_k,   g_k32);
    cudaGetSymbolAddress((void**)&p_vT,  g_vT32);
    cudaGetSymbolAddress((void**)&p_o,   g_o32);

    cudaFuncSetAttribute(gemm_tf32,
        cudaFuncAttributeMaxDynamicSharedMemorySize, GEMM_SMEM);
    cudaFuncSetAttribute(attn_tf32,
        cudaFuncAttributeMaxDynamicSharedMemorySize, ATT_SMEM);

    // 0) round+permute inputs / weights
    {
        int n4;
        n4 = (M_ * D_) / 4;
        cvt_perm4<<<(n4 + 255) / 256, 256>>>(x, p_x, n4, D_);
        n4 = (NQKV * D_) / 4;
        cvt_perm4<<<(n4 + 255) / 256, 256>>>(w_qkv, p_wq, n4, D_);
        n4 = (D_ * D_) / 4;
        cvt_perm4<<<(n4 + 255) / 256, 256>>>(w_out, p_wo, n4, D_);
    }
    // 1) QKV projection: [4096 x 1024] x [3072 x 1024]^T
    {
        dim3 grid(NQKV / 128, M_ / 256);
        gemm_tf32<<<grid, 256, GEMM_SMEM>>>(p_x, p_wq, nullptr, p_qkv,
                                            M_, NQKV, D_);
    }
    // 2) RoPE -> tf32 q/k/vT
    {
        int total = B_ * S_ * H_ * 32;
        rope_tf32<<<(total + 255) / 256, 256>>>(p_qkv, p_q, p_k, p_vT);
    }
    // 3) flash attention
    {
        dim3 grid(S_ / 128, H_, B_);
        attn_tf32<<<grid, 128, ATT_SMEM>>>(p_q, p_k, p_vT, p_o);
    }
    // 4) output projection + bias
    {
        dim3 grid(D_ / 128, M_ / 256);
        gemm_tf32<<<grid, 256, GEMM_SMEM>>>(p_o, p_wo, b_out, out,
                                            M_, D_, D_);
    }
}